// round 1
// baseline (speedup 1.0000x reference)
#include <cuda_runtime.h>
#include <math.h>

// Problem constants
namespace {
constexpr int kB    = 4;
constexpr int kLQ   = 1024;
constexpr int kD    = 2048;
constexpr int kH    = 16;
constexpr int kG    = 4;
constexpr int kHD   = 128;
constexpr int kGS   = 4;      // H / G
constexpr int kPAST = 1024;
constexpr int kLK   = 2048;   // PAST + LQ
constexpr int kM    = kB * kLQ;          // 4096
constexpr int kNQ   = kD;                // 2048
constexpr int kNKV  = kG * kHD;          // 512
constexpr int kNTOT = kNQ + 2 * kNKV;    // 3072
constexpr float kScale = 0.08838834764831845f; // 1/sqrt(128)
}

// Scratch (allocation-free rule: device globals)
__device__ float g_q  [kB * kH * kLQ * kHD];   // (b,h,t,d)
__device__ float g_kc [kB * kG * kLK * kHD];   // (b,g,p,d) concat cache
__device__ float g_vc [kB * kG * kLK * kHD];   // (b,g,p,d)
__device__ float g_att[kB * kLQ * kD];         // (b,t,h*HD)

// ---------------------------------------------------------------------------
// Kernel 1: copy past_k/past_v into the (B,G,LK,HD) caches (front section)
// ---------------------------------------------------------------------------
__global__ void copy_past_kernel(const float4* __restrict__ pk,
                                 const float4* __restrict__ pv) {
    constexpr int chunk4 = kPAST * kHD / 4;      // 32768 float4 per (b,g)
    constexpr int dst4   = kLK * kHD / 4;        // 65536 float4 per (b,g)
    constexpr int total4 = kB * kG * chunk4;     // 524288
    int i = blockIdx.x * blockDim.x + threadIdx.x;
    if (i < total4) {
        int cg  = i / chunk4;
        int rem = i - cg * chunk4;
        ((float4*)g_kc)[cg * dst4 + rem] = pk[i];
        ((float4*)g_vc)[cg * dst4 + rem] = pv[i];
    }
}

// ---------------------------------------------------------------------------
// Kernel 2: fused QKV projection GEMM + bias + RoPE + scatter to q / caches
// Tiles: BM=64, BN=64, BK=16; 256 threads, 4x4 micro-tile per thread.
// ---------------------------------------------------------------------------
__global__ __launch_bounds__(256) void qkv_kernel(
    const float* __restrict__ x,  const float* __restrict__ rf,
    const float* __restrict__ Wq, const float* __restrict__ bq,
    const float* __restrict__ Wk, const float* __restrict__ bk,
    const float* __restrict__ Wv, const float* __restrict__ bv) {

    __shared__ float As[16][64];   // [k][m]
    __shared__ float Bs[16][64];   // [k][n]

    const int n0  = blockIdx.x * 64;    // fused column
    const int m0  = blockIdx.y * 64;
    const int tid = threadIdx.x;
    const int tm  = tid >> 4;           // 0..15 (row group)
    const int tn  = tid & 15;           // 0..15 (col group)

    // segment select (block never straddles a boundary: 2048, 2560 are /64)
    const float* W; const float* bias; int nloc; int Nw; int seg;
    if (n0 < kNQ)              { W = Wq; bias = bq; nloc = n0;                Nw = kNQ;  seg = 0; }
    else if (n0 < kNQ + kNKV)  { W = Wk; bias = bk; nloc = n0 - kNQ;          Nw = kNKV; seg = 1; }
    else                       { W = Wv; bias = bv; nloc = n0 - kNQ - kNKV;   Nw = kNKV; seg = 2; }

    const int arow = tid >> 2, akq = tid & 3;   // x loader: 64 rows x 4 float4
    const int bkk  = tid >> 4, bnq = tid & 15;  // W loader: 16 rows x 16 float4

    float acc[4][4] = {};

    for (int k0 = 0; k0 < kD; k0 += 16) {
        float4 av  = *(const float4*)&x[(m0 + arow) * kD + k0 + akq * 4];
        float4 bv4 = *(const float4*)&W[(k0 + bkk) * Nw + nloc + bnq * 4];
        __syncthreads();
        As[akq * 4 + 0][arow] = av.x;
        As[akq * 4 + 1][arow] = av.y;
        As[akq * 4 + 2][arow] = av.z;
        As[akq * 4 + 3][arow] = av.w;
        *(float4*)&Bs[bkk][bnq * 4] = bv4;
        __syncthreads();
#pragma unroll
        for (int kk = 0; kk < 16; kk++) {
            float a[4], b[4];
            *(float4*)a = *(const float4*)&As[kk][tm * 4];
            *(float4*)b = *(const float4*)&Bs[kk][tn * 4];
#pragma unroll
            for (int i = 0; i < 4; i++)
#pragma unroll
                for (int j = 0; j < 4; j++) acc[i][j] += a[i] * b[j];
        }
    }

    // Epilogue: bias + RoPE (q,k) + scatter
#pragma unroll
    for (int i = 0; i < 4; i++) {
        const int m = m0 + tm * 4 + i;
        const int b = m >> 10;            // / LQ
        const int t = m & (kLQ - 1);
#pragma unroll
        for (int jp = 0; jp < 2; jp++) {
            const int n  = nloc + tn * 4 + jp * 2;   // segment-local column (even)
            float v0 = acc[i][jp * 2 + 0] + bias[n];
            float v1 = acc[i][jp * 2 + 1] + bias[n + 1];
            const int d = n & 127;
            if (seg == 0) {
                const int h = n >> 7;
                float sn, cs; sincosf(rf[t * (kHD / 2) + (d >> 1)], &sn, &cs);
                float r0 = v0 * cs - v1 * sn;
                float r1 = v0 * sn + v1 * cs;
                float* dst = &g_q[(((b * kH + h) * kLQ + t) * kHD) + d];
                dst[0] = r0; dst[1] = r1;
            } else if (seg == 1) {
                const int g = n >> 7;
                float sn, cs; sincosf(rf[t * (kHD / 2) + (d >> 1)], &sn, &cs);
                float r0 = v0 * cs - v1 * sn;
                float r1 = v0 * sn + v1 * cs;
                float* dst = &g_kc[(((b * kG + g) * kLK + kPAST + t) * kHD) + d];
                dst[0] = r0; dst[1] = r1;
            } else {
                const int g = n >> 7;
                float* dst = &g_vc[(((b * kG + g) * kLK + kPAST + t) * kHD) + d];
                dst[0] = v0; dst[1] = v1;
            }
        }
    }
}

// ---------------------------------------------------------------------------
// Kernel 3: flash attention, fp32, BQ=64, BK=64, 256 threads.
// grid = (LQ/64, H, B). Causal with offset PAST.
// ---------------------------------------------------------------------------
constexpr int QK_LD = 132;   // padded row stride for Qs/Ks (conflict control)
constexpr int SS_LD = 65;    // padded row stride for S
constexpr int ATTN_SMEM_FLOATS = 64 * QK_LD * 2 + 64 * 128 + 64 * SS_LD + 3 * 64;
constexpr int ATTN_SMEM_BYTES  = ATTN_SMEM_FLOATS * 4; // 117760

__global__ __launch_bounds__(256) void attn_kernel() {
    extern __shared__ float sm[];
    float* Qs   = sm;                      // 64 x QK_LD
    float* Ks   = Qs + 64 * QK_LD;         // 64 x QK_LD
    float* Vs   = Ks + 64 * QK_LD;         // 64 x 128
    float* Ss   = Vs + 64 * 128;           // 64 x SS_LD
    float* mrow = Ss + 64 * SS_LD;
    float* lrow = mrow + 64;
    float* arw  = lrow + 64;

    const int qb = blockIdx.x;             // 0..15
    const int h  = blockIdx.y;             // 0..15
    const int b  = blockIdx.z;             // 0..3
    const int g  = h >> 2;                 // GQA group
    const int t0 = qb * 64;
    const int tid = threadIdx.x;
    const int tm = tid >> 4, tn = tid & 15;   // GEMM1 4x4 micro-tile
    const int ry = tid >> 4, cx = tid & 15;   // GEMM2: 4 rows x 8 cols

    // Load Q tile
    const float* qbase = g_q + ((size_t)(b * kH + h) * kLQ + t0) * kHD;
#pragma unroll
    for (int it = 0; it < 8; it++) {
        int idx = tid + it * 256;
        int r = idx >> 5, dq = (idx & 31) * 4;
        *(float4*)&Qs[r * QK_LD + dq] = *(const float4*)&qbase[r * kHD + dq];
    }
    if (tid < 64) { mrow[tid] = -1e30f; lrow[tid] = 0.f; }

    float o[4][8] = {};

    const float* kbase = g_kc + (size_t)(b * kG + g) * kLK * kHD;
    const float* vbase = g_vc + (size_t)(b * kG + g) * kLK * kHD;
    const int ntiles = (kPAST + t0) / 64 + 1;

    for (int kt = 0; kt < ntiles; kt++) {
        const int k0 = kt * 64;
        __syncthreads();  // protect Ks/Vs/Ss of previous iteration
#pragma unroll
        for (int it = 0; it < 8; it++) {
            int idx = tid + it * 256;
            int r = idx >> 5, dq = (idx & 31) * 4;
            *(float4*)&Ks[r * QK_LD + dq] = *(const float4*)&kbase[(size_t)(k0 + r) * kHD + dq];
            *(float4*)&Vs[r * 128   + dq] = *(const float4*)&vbase[(size_t)(k0 + r) * kHD + dq];
        }
        __syncthreads();

        // GEMM1: S = Q . K^T
        float s[4][4] = {};
        for (int d = 0; d < 128; d += 4) {
            float4 qv[4], kv[4];
#pragma unroll
            for (int i = 0; i < 4; i++) qv[i] = *(const float4*)&Qs[(tm * 4 + i) * QK_LD + d];
#pragma unroll
            for (int j = 0; j < 4; j++) kv[j] = *(const float4*)&Ks[(tn * 4 + j) * QK_LD + d];
#pragma unroll
            for (int i = 0; i < 4; i++)
#pragma unroll
                for (int j = 0; j < 4; j++)
                    s[i][j] += qv[i].x * kv[j].x + qv[i].y * kv[j].y
                             + qv[i].z * kv[j].z + qv[i].w * kv[j].w;
        }
        // scale + causal mask + store to smem
#pragma unroll
        for (int i = 0; i < 4; i++) {
            const int qpos = kPAST + t0 + tm * 4 + i;
#pragma unroll
            for (int j = 0; j < 4; j++) {
                const int kpos = k0 + tn * 4 + j;
                float val = s[i][j] * kScale;
                if (kpos > qpos) val = -1e30f;
                Ss[(tm * 4 + i) * SS_LD + tn * 4 + j] = val;
            }
        }
        __syncthreads();

        // Online softmax (one thread per row)
        if (tid < 64) {
            const int r = tid;
            float m_old = mrow[r];
            float mmax = m_old;
            for (int c = 0; c < 64; c++) mmax = fmaxf(mmax, Ss[r * SS_LD + c]);
            float alpha = __expf(m_old - mmax);
            float sum = 0.f;
            for (int c = 0; c < 64; c++) {
                float p = __expf(Ss[r * SS_LD + c] - mmax);
                Ss[r * SS_LD + c] = p;
                sum += p;
            }
            mrow[r] = mmax;
            lrow[r] = lrow[r] * alpha + sum;
            arw[r]  = alpha;
        }
        __syncthreads();

        // GEMM2: O = O*alpha + P . V
#pragma unroll
        for (int i = 0; i < 4; i++) {
            float al = arw[ry * 4 + i];
#pragma unroll
            for (int j = 0; j < 8; j++) o[i][j] *= al;
        }
        for (int kk = 0; kk < 64; kk++) {
            float4 va = *(const float4*)&Vs[kk * 128 + cx * 8];
            float4 vb = *(const float4*)&Vs[kk * 128 + cx * 8 + 4];
#pragma unroll
            for (int i = 0; i < 4; i++) {
                float p = Ss[(ry * 4 + i) * SS_LD + kk];
                o[i][0] += p * va.x; o[i][1] += p * va.y;
                o[i][2] += p * va.z; o[i][3] += p * va.w;
                o[i][4] += p * vb.x; o[i][5] += p * vb.y;
                o[i][6] += p * vb.z; o[i][7] += p * vb.w;
            }
        }
    }

    // Normalize + store to (b, t, h*HD + c)
#pragma unroll
    for (int i = 0; i < 4; i++) {
        const int r = ry * 4 + i;
        const float inv = 1.f / lrow[r];
        const int t = t0 + r;
        float* dst = &g_att[((size_t)(b * kLQ + t)) * kD + h * kHD + cx * 8];
        float4 w0, w1;
        w0.x = o[i][0] * inv; w0.y = o[i][1] * inv; w0.z = o[i][2] * inv; w0.w = o[i][3] * inv;
        w1.x = o[i][4] * inv; w1.y = o[i][5] * inv; w1.z = o[i][6] * inv; w1.w = o[i][7] * inv;
        *(float4*)&dst[0] = w0;
        *(float4*)&dst[4] = w1;
    }
}

// ---------------------------------------------------------------------------
// Kernel 4: output GEMM  out = g_att @ Wo + bo   (4096 x 2048 x 2048)
// ---------------------------------------------------------------------------
__global__ __launch_bounds__(256) void out_kernel(
    const float* __restrict__ Wo, const float* __restrict__ bo,
    float* __restrict__ out) {

    __shared__ float As[16][64];
    __shared__ float Bs[16][64];

    const int n0  = blockIdx.x * 64;
    const int m0  = blockIdx.y * 64;
    const int tid = threadIdx.x;
    const int tm  = tid >> 4;
    const int tn  = tid & 15;
    const int arow = tid >> 2, akq = tid & 3;
    const int bkk  = tid >> 4, bnq = tid & 15;

    float acc[4][4] = {};

    for (int k0 = 0; k0 < kD; k0 += 16) {
        float4 av  = *(const float4*)&g_att[(size_t)(m0 + arow) * kD + k0 + akq * 4];
        float4 bv4 = *(const float4*)&Wo[(size_t)(k0 + bkk) * kD + n0 + bnq * 4];
        __syncthreads();
        As[akq * 4 + 0][arow] = av.x;
        As[akq * 4 + 1][arow] = av.y;
        As[akq * 4 + 2][arow] = av.z;
        As[akq * 4 + 3][arow] = av.w;
        *(float4*)&Bs[bkk][bnq * 4] = bv4;
        __syncthreads();
#pragma unroll
        for (int kk = 0; kk < 16; kk++) {
            float a[4], b[4];
            *(float4*)a = *(const float4*)&As[kk][tm * 4];
            *(float4*)b = *(const float4*)&Bs[kk][tn * 4];
#pragma unroll
            for (int i = 0; i < 4; i++)
#pragma unroll
                for (int j = 0; j < 4; j++) acc[i][j] += a[i] * b[j];
        }
    }

#pragma unroll
    for (int i = 0; i < 4; i++) {
        const int m = m0 + tm * 4 + i;
        float4 r;
        r.x = acc[i][0] + bo[n0 + tn * 4 + 0];
        r.y = acc[i][1] + bo[n0 + tn * 4 + 1];
        r.z = acc[i][2] + bo[n0 + tn * 4 + 2];
        r.w = acc[i][3] + bo[n0 + tn * 4 + 3];
        *(float4*)&out[(size_t)m * kD + n0 + tn * 4] = r;
    }
}

// ---------------------------------------------------------------------------
// Launch
// Inputs: x, mask, rotary_freqs, past_k, past_v, Wq, bq, Wk, bk, Wv, bv, Wo, bo
// (mask is implied by the causal structure; we don't read it)
// ---------------------------------------------------------------------------
extern "C" void kernel_launch(void* const* d_in, const int* in_sizes, int n_in,
                              void* d_out, int out_size) {
    const float* x  = (const float*)d_in[0];
    const float* rf = (const float*)d_in[2];
    const float* pk = (const float*)d_in[3];
    const float* pv = (const float*)d_in[4];
    const float* Wq = (const float*)d_in[5];
    const float* bq = (const float*)d_in[6];
    const float* Wk = (const float*)d_in[7];
    const float* bk = (const float*)d_in[8];
    const float* Wv = (const float*)d_in[9];
    const float* bv = (const float*)d_in[10];
    const float* Wo = (const float*)d_in[11];
    const float* bo = (const float*)d_in[12];
    float* out = (float*)d_out;

    cudaFuncSetAttribute(attn_kernel,
                         cudaFuncAttributeMaxDynamicSharedMemorySize,
                         ATTN_SMEM_BYTES);

    copy_past_kernel<<<2048, 256>>>((const float4*)pk, (const float4*)pv);
    qkv_kernel<<<dim3(kNTOT / 64, kM / 64), 256>>>(x, rf, Wq, bq, Wk, bk, Wv, bv);
    attn_kernel<<<dim3(kLQ / 64, kH, kB), 256, ATTN_SMEM_BYTES>>>();
    out_kernel<<<dim3(kD / 64, kM / 64), 256>>>(Wo, bo, out);
}

// round 2
// speedup vs baseline: 1.5256x; 1.5256x over previous
#include <cuda_runtime.h>
#include <math.h>

// Problem constants
namespace {
constexpr int kB    = 4;
constexpr int kLQ   = 1024;
constexpr int kD    = 2048;
constexpr int kH    = 16;
constexpr int kG    = 4;
constexpr int kHD   = 128;
constexpr int kPAST = 1024;
constexpr int kLK   = 2048;   // PAST + LQ
constexpr int kM    = kB * kLQ;          // 4096
constexpr int kNQ   = kD;                // 2048
constexpr int kNKV  = kG * kHD;          // 512
constexpr int kNTOT = kNQ + 2 * kNKV;    // 3072
constexpr float kScale = 0.08838834764831845f; // 1/sqrt(128)
}

// Scratch (allocation-free rule: device globals)
__device__ float g_q  [kB * kH * kLQ * kHD];   // (b,h,t,d)
__device__ float g_kc [kB * kG * kLK * kHD];   // (b,g,p,d) concat cache
__device__ float g_vc [kB * kG * kLK * kHD];   // (b,g,p,d)
__device__ float g_att[kB * kLQ * kD];         // (b,t,h*HD)

// ---------------------------------------------------------------------------
// f32x2 packed-math helpers (Blackwell FFMA2 — only reachable via PTX)
// ---------------------------------------------------------------------------
__device__ __forceinline__ unsigned long long dup2(float x) {
    unsigned long long r;
    unsigned u = __float_as_uint(x);
    asm("mov.b64 %0, {%1, %1};" : "=l"(r) : "r"(u));
    return r;
}
__device__ __forceinline__ void ffma2(unsigned long long& d,
                                      unsigned long long a,
                                      unsigned long long b) {
    asm("fma.rn.f32x2 %0, %1, %2, %0;" : "+l"(d) : "l"(a), "l"(b));
}
__device__ __forceinline__ void mul2(unsigned long long& d, unsigned long long a) {
    asm("mul.rn.f32x2 %0, %0, %1;" : "+l"(d) : "l"(a));
}
__device__ __forceinline__ float2 u2f(unsigned long long u) {
    unsigned lo, hi;
    asm("mov.b64 {%0, %1}, %2;" : "=r"(lo), "=r"(hi) : "l"(u));
    return make_float2(__uint_as_float(lo), __uint_as_float(hi));
}

// ---------------------------------------------------------------------------
// Kernel 1: copy past_k/past_v into the (B,G,LK,HD) caches (front section)
// ---------------------------------------------------------------------------
__global__ void copy_past_kernel(const float4* __restrict__ pk,
                                 const float4* __restrict__ pv) {
    constexpr int chunk4 = kPAST * kHD / 4;      // 32768 float4 per (b,g)
    constexpr int dst4   = kLK * kHD / 4;        // 65536 float4 per (b,g)
    constexpr int total4 = kB * kG * chunk4;     // 524288
    int i = blockIdx.x * blockDim.x + threadIdx.x;
    if (i < total4) {
        int cg  = i / chunk4;
        int rem = i - cg * chunk4;
        ((float4*)g_kc)[cg * dst4 + rem] = pk[i];
        ((float4*)g_vc)[cg * dst4 + rem] = pv[i];
    }
}

// ---------------------------------------------------------------------------
// Kernel 2: fused QKV projection GEMM + bias + RoPE + scatter
// 128x128 tile, BK=16, 256 threads, 8x8 micro-tile, f32x2 FMA.
// ---------------------------------------------------------------------------
__global__ __launch_bounds__(256, 1) void qkv_kernel(
    const float* __restrict__ x,  const float* __restrict__ rf,
    const float* __restrict__ Wq, const float* __restrict__ bq,
    const float* __restrict__ Wk, const float* __restrict__ bk,
    const float* __restrict__ Wv, const float* __restrict__ bv) {

    __shared__ float As[16][132];   // [k][m]
    __shared__ float Bs[16][132];   // [k][n]

    const int n0  = blockIdx.x * 128;   // fused column
    const int m0  = blockIdx.y * 128;
    const int tid = threadIdx.x;
    const int tm  = tid >> 4;           // 0..15
    const int tn  = tid & 15;           // 0..15

    // segment select (2048 and 2560 are both multiples of 128)
    const float* W; const float* bias; int nloc; int Nw; int seg;
    if (n0 < kNQ)              { W = Wq; bias = bq; nloc = n0;              Nw = kNQ;  seg = 0; }
    else if (n0 < kNQ + kNKV)  { W = Wk; bias = bk; nloc = n0 - kNQ;        Nw = kNKV; seg = 1; }
    else                       { W = Wv; bias = bv; nloc = n0 - kNQ - kNKV; Nw = kNKV; seg = 2; }

    const int arow = tid >> 2, akq = tid & 3;   // x loader
    const int bkk  = tid >> 4, bnq = tid & 15;  // W loader

    unsigned long long acc2[4][8];
#pragma unroll
    for (int i = 0; i < 4; i++)
#pragma unroll
        for (int j = 0; j < 8; j++) acc2[i][j] = 0ull;

    for (int k0 = 0; k0 < kD; k0 += 16) {
        float4 a0 = *(const float4*)&x[(size_t)(m0 + arow) * kD + k0 + akq * 4];
        float4 a1 = *(const float4*)&x[(size_t)(m0 + arow + 64) * kD + k0 + akq * 4];
        float4 b0 = *(const float4*)&W[(size_t)(k0 + bkk) * Nw + nloc + bnq * 4];
        float4 b1 = *(const float4*)&W[(size_t)(k0 + bkk) * Nw + nloc + (bnq + 16) * 4];
        __syncthreads();
        As[akq * 4 + 0][arow] = a0.x;  As[akq * 4 + 1][arow] = a0.y;
        As[akq * 4 + 2][arow] = a0.z;  As[akq * 4 + 3][arow] = a0.w;
        As[akq * 4 + 0][arow + 64] = a1.x;  As[akq * 4 + 1][arow + 64] = a1.y;
        As[akq * 4 + 2][arow + 64] = a1.z;  As[akq * 4 + 3][arow + 64] = a1.w;
        *(float4*)&Bs[bkk][bnq * 4] = b0;
        *(float4*)&Bs[bkk][(bnq + 16) * 4] = b1;
        __syncthreads();
#pragma unroll
        for (int kk = 0; kk < 16; kk++) {
            ulonglong2 aa = *(const ulonglong2*)&As[kk][tm * 8];
            ulonglong2 ab = *(const ulonglong2*)&As[kk][tm * 8 + 4];
            float4 bv0 = *(const float4*)&Bs[kk][tn * 8];
            float4 bv1 = *(const float4*)&Bs[kk][tn * 8 + 4];
            unsigned long long a2[4] = {aa.x, aa.y, ab.x, ab.y};
            unsigned long long bd[8] = {dup2(bv0.x), dup2(bv0.y), dup2(bv0.z), dup2(bv0.w),
                                        dup2(bv1.x), dup2(bv1.y), dup2(bv1.z), dup2(bv1.w)};
#pragma unroll
            for (int i = 0; i < 4; i++)
#pragma unroll
                for (int j = 0; j < 8; j++) ffma2(acc2[i][j], a2[i], bd[j]);
        }
    }

    // Epilogue: bias + RoPE (q,k) + scatter
#pragma unroll
    for (int i = 0; i < 8; i++) {
        const int m = m0 + tm * 8 + i;
        const int b = m >> 10;
        const int t = m & (kLQ - 1);
        float av[8];
#pragma unroll
        for (int j = 0; j < 8; j++) {
            float2 f = u2f(acc2[i >> 1][j]);
            av[j] = (i & 1) ? f.y : f.x;
        }
#pragma unroll
        for (int jp = 0; jp < 4; jp++) {
            const int n  = nloc + tn * 8 + jp * 2;   // even
            float v0 = av[jp * 2 + 0] + bias[n];
            float v1 = av[jp * 2 + 1] + bias[n + 1];
            const int d = n & 127;
            if (seg == 0) {
                const int h = n >> 7;
                float sn, cs; sincosf(rf[t * (kHD / 2) + (d >> 1)], &sn, &cs);
                float r0 = v0 * cs - v1 * sn;
                float r1 = v0 * sn + v1 * cs;
                float* dst = &g_q[((size_t)((b * kH + h) * kLQ + t) * kHD) + d];
                dst[0] = r0; dst[1] = r1;
            } else if (seg == 1) {
                const int g = n >> 7;
                float sn, cs; sincosf(rf[t * (kHD / 2) + (d >> 1)], &sn, &cs);
                float r0 = v0 * cs - v1 * sn;
                float r1 = v0 * sn + v1 * cs;
                float* dst = &g_kc[((size_t)((b * kG + g) * kLK + kPAST + t) * kHD) + d];
                dst[0] = r0; dst[1] = r1;
            } else {
                const int g = n >> 7;
                float* dst = &g_vc[((size_t)((b * kG + g) * kLK + kPAST + t) * kHD) + d];
                dst[0] = v0; dst[1] = v1;
            }
        }
    }
}

// ---------------------------------------------------------------------------
// Kernel 3: flash attention, fp32, BQ=128, BK=64, 256 threads.
// Register softmax + f32x2 FMA. grid = (LQ/128, H, B).
// ---------------------------------------------------------------------------
constexpr int QS_FLOATS = 128 * 128;   // [d][t]
constexpr int KS_STRIDE = 68;
constexpr int KS_FLOATS = 128 * KS_STRIDE;  // [d][c]
constexpr int VS_FLOATS = 64 * 128;    // [kk][n]
constexpr int SS_STRIDE = 68;
constexpr int SS_FLOATS = 128 * SS_STRIDE;  // [r][kk]
constexpr int ATTN_SMEM_BYTES = (QS_FLOATS + KS_FLOATS + VS_FLOATS + SS_FLOATS) * 4;

__global__ __launch_bounds__(256, 1) void attn_kernel() {
    extern __shared__ float sm[];
    float* Qs = sm;                         // 128 x 128  (d-major)
    float* Ks = Qs + QS_FLOATS;             // 128 x 68   (d-major)
    float* Vs = Ks + KS_FLOATS;             // 64 x 128
    float* Ss = Vs + VS_FLOATS;             // 128 x 68

    const int qb = blockIdx.x;              // 0..7
    const int h  = blockIdx.y;
    const int b  = blockIdx.z;
    const int g  = h >> 2;
    const int t0 = qb * 128;
    const int tid = threadIdx.x;
    const int tm = tid >> 4, tn = tid & 15;

    // Load Q tile transposed, pre-scaled
    const float* qbase = g_q + ((size_t)(b * kH + h) * kLQ + t0) * kHD;
    {
        const int t = tid & 127, half = tid >> 7;
#pragma unroll
        for (int it = 0; it < 16; it++) {
            int d0 = half * 64 + it * 4;
            float4 v = *(const float4*)&qbase[(size_t)t * kHD + d0];
            Qs[(d0 + 0) * 128 + t] = v.x * kScale;
            Qs[(d0 + 1) * 128 + t] = v.y * kScale;
            Qs[(d0 + 2) * 128 + t] = v.z * kScale;
            Qs[(d0 + 3) * 128 + t] = v.w * kScale;
        }
    }

    float m_i[8], l_i[8];
    unsigned long long o2[8][4];
#pragma unroll
    for (int i = 0; i < 8; i++) {
        m_i[i] = -1e30f; l_i[i] = 0.f;
#pragma unroll
        for (int j = 0; j < 4; j++) o2[i][j] = 0ull;
    }

    const float* kbase = g_kc + (size_t)(b * kG + g) * kLK * kHD;
    const float* vbase = g_vc + (size_t)(b * kG + g) * kLK * kHD;
    const int ntiles = (kPAST + t0) / 64 + 2;

    for (int kt = 0; kt < ntiles; kt++) {
        const int k0 = kt * 64;
        __syncthreads();
        // K transposed into Ks[d][c]
        {
            const int c = tid & 63, grp = tid >> 6;
#pragma unroll
            for (int it = 0; it < 8; it++) {
                int d0 = grp * 32 + it * 4;
                float4 v = *(const float4*)&kbase[(size_t)(k0 + c) * kHD + d0];
                Ks[(d0 + 0) * KS_STRIDE + c] = v.x;
                Ks[(d0 + 1) * KS_STRIDE + c] = v.y;
                Ks[(d0 + 2) * KS_STRIDE + c] = v.z;
                Ks[(d0 + 3) * KS_STRIDE + c] = v.w;
            }
#pragma unroll
            for (int it = 0; it < 8; it++) {
                int idx = tid + it * 256;
                int kk = idx >> 5, d4 = (idx & 31) * 4;
                *(float4*)&Vs[kk * 128 + d4] =
                    *(const float4*)&vbase[(size_t)(k0 + kk) * kHD + d4];
            }
        }
        __syncthreads();

        // GEMM1: S = Q^T-tile . K-tile  (per-thread 8 rows x 4 cols)
        unsigned long long s2[4][4];
#pragma unroll
        for (int i = 0; i < 4; i++)
#pragma unroll
            for (int j = 0; j < 4; j++) s2[i][j] = 0ull;

#pragma unroll 4
        for (int d = 0; d < 128; d++) {
            ulonglong2 qa = *(const ulonglong2*)&Qs[d * 128 + tm * 8];
            ulonglong2 qc = *(const ulonglong2*)&Qs[d * 128 + tm * 8 + 4];
            float4 kv = *(const float4*)&Ks[d * KS_STRIDE + tn * 4];
            unsigned long long a2[4] = {qa.x, qa.y, qc.x, qc.y};
            unsigned long long kd[4] = {dup2(kv.x), dup2(kv.y), dup2(kv.z), dup2(kv.w)};
#pragma unroll
            for (int i = 0; i < 4; i++)
#pragma unroll
                for (int j = 0; j < 4; j++) ffma2(s2[i][j], a2[i], kd[j]);
        }

        // unpack + causal mask
        float s[8][4];
#pragma unroll
        for (int i2 = 0; i2 < 4; i2++)
#pragma unroll
            for (int j = 0; j < 4; j++) {
                float2 f = u2f(s2[i2][j]);
                s[2 * i2 + 0][j] = f.x;
                s[2 * i2 + 1][j] = f.y;
            }
        if (k0 + 63 > kPAST + t0) {
#pragma unroll
            for (int i = 0; i < 8; i++) {
                const int qpos = kPAST + t0 + tm * 8 + i;
#pragma unroll
                for (int j = 0; j < 4; j++)
                    if (k0 + tn * 4 + j > qpos) s[i][j] = -1e30f;
            }
        }

        // register softmax (row groups of 16 lanes)
        float alpha_i[8];
#pragma unroll
        for (int i = 0; i < 8; i++) {
            float mx = fmaxf(fmaxf(s[i][0], s[i][1]), fmaxf(s[i][2], s[i][3]));
#pragma unroll
            for (int off = 1; off < 16; off <<= 1)
                mx = fmaxf(mx, __shfl_xor_sync(0xffffffffu, mx, off));
            float mnew = fmaxf(m_i[i], mx);
            float al = __expf(m_i[i] - mnew);
            float4 p;
            p.x = __expf(s[i][0] - mnew);
            p.y = __expf(s[i][1] - mnew);
            p.z = __expf(s[i][2] - mnew);
            p.w = __expf(s[i][3] - mnew);
            float sum = (p.x + p.y) + (p.z + p.w);
#pragma unroll
            for (int off = 1; off < 16; off <<= 1)
                sum += __shfl_xor_sync(0xffffffffu, sum, off);
            l_i[i] = l_i[i] * al + sum;
            m_i[i] = mnew;
            alpha_i[i] = al;
            *(float4*)&Ss[(tm * 8 + i) * SS_STRIDE + tn * 4] = p;
        }

        // rescale O by alpha (no smem dependency — before sync)
#pragma unroll
        for (int i = 0; i < 8; i++) {
            unsigned long long ad = dup2(alpha_i[i]);
#pragma unroll
            for (int j = 0; j < 4; j++) mul2(o2[i][j], ad);
        }
        __syncthreads();

        // GEMM2: O += P . V  (per-thread 8 rows x 8 cols)
#pragma unroll 2
        for (int kk = 0; kk < 64; kk++) {
            ulonglong2 va = *(const ulonglong2*)&Vs[kk * 128 + tn * 8];
            ulonglong2 vb = *(const ulonglong2*)&Vs[kk * 128 + tn * 8 + 4];
            unsigned long long v2[4] = {va.x, va.y, vb.x, vb.y};
#pragma unroll
            for (int i = 0; i < 8; i++) {
                unsigned long long pd = dup2(Ss[(tm * 8 + i) * SS_STRIDE + kk]);
#pragma unroll
                for (int j = 0; j < 4; j++) ffma2(o2[i][j], pd, v2[j]);
            }
        }
    }

    // Normalize + store
#pragma unroll
    for (int i = 0; i < 8; i++) {
        const float inv = 1.f / l_i[i];
        const int t = t0 + tm * 8 + i;
        float* dst = &g_att[((size_t)(b * kLQ + t)) * kD + h * kHD + tn * 8];
        float2 p0 = u2f(o2[i][0]), p1 = u2f(o2[i][1]);
        float2 p2 = u2f(o2[i][2]), p3 = u2f(o2[i][3]);
        float4 w0 = {p0.x * inv, p0.y * inv, p1.x * inv, p1.y * inv};
        float4 w1 = {p2.x * inv, p2.y * inv, p3.x * inv, p3.y * inv};
        *(float4*)&dst[0] = w0;
        *(float4*)&dst[4] = w1;
    }
}

// ---------------------------------------------------------------------------
// Kernel 4: output GEMM  out = g_att @ Wo + bo   (4096 x 2048 x 2048)
// 128x128 tile, BK=16, 8x8 micro-tile, f32x2.
// ---------------------------------------------------------------------------
__global__ __launch_bounds__(256, 1) void out_kernel(
    const float* __restrict__ Wo, const float* __restrict__ bo,
    float* __restrict__ out) {

    __shared__ float As[16][132];
    __shared__ float Bs[16][132];

    const int n0  = blockIdx.x * 128;
    const int m0  = blockIdx.y * 128;
    const int tid = threadIdx.x;
    const int tm  = tid >> 4;
    const int tn  = tid & 15;
    const int arow = tid >> 2, akq = tid & 3;
    const int bkk  = tid >> 4, bnq = tid & 15;

    unsigned long long acc2[4][8];
#pragma unroll
    for (int i = 0; i < 4; i++)
#pragma unroll
        for (int j = 0; j < 8; j++) acc2[i][j] = 0ull;

    for (int k0 = 0; k0 < kD; k0 += 16) {
        float4 a0 = *(const float4*)&g_att[(size_t)(m0 + arow) * kD + k0 + akq * 4];
        float4 a1 = *(const float4*)&g_att[(size_t)(m0 + arow + 64) * kD + k0 + akq * 4];
        float4 b0 = *(const float4*)&Wo[(size_t)(k0 + bkk) * kD + n0 + bnq * 4];
        float4 b1 = *(const float4*)&Wo[(size_t)(k0 + bkk) * kD + n0 + (bnq + 16) * 4];
        __syncthreads();
        As[akq * 4 + 0][arow] = a0.x;  As[akq * 4 + 1][arow] = a0.y;
        As[akq * 4 + 2][arow] = a0.z;  As[akq * 4 + 3][arow] = a0.w;
        As[akq * 4 + 0][arow + 64] = a1.x;  As[akq * 4 + 1][arow + 64] = a1.y;
        As[akq * 4 + 2][arow + 64] = a1.z;  As[akq * 4 + 3][arow + 64] = a1.w;
        *(float4*)&Bs[bkk][bnq * 4] = b0;
        *(float4*)&Bs[bkk][(bnq + 16) * 4] = b1;
        __syncthreads();
#pragma unroll
        for (int kk = 0; kk < 16; kk++) {
            ulonglong2 aa = *(const ulonglong2*)&As[kk][tm * 8];
            ulonglong2 ab = *(const ulonglong2*)&As[kk][tm * 8 + 4];
            float4 bv0 = *(const float4*)&Bs[kk][tn * 8];
            float4 bv1 = *(const float4*)&Bs[kk][tn * 8 + 4];
            unsigned long long a2[4] = {aa.x, aa.y, ab.x, ab.y};
            unsigned long long bd[8] = {dup2(bv0.x), dup2(bv0.y), dup2(bv0.z), dup2(bv0.w),
                                        dup2(bv1.x), dup2(bv1.y), dup2(bv1.z), dup2(bv1.w)};
#pragma unroll
            for (int i = 0; i < 4; i++)
#pragma unroll
                for (int j = 0; j < 8; j++) ffma2(acc2[i][j], a2[i], bd[j]);
        }
    }

#pragma unroll
    for (int i = 0; i < 8; i++) {
        const int m = m0 + tm * 8 + i;
        float av[8];
#pragma unroll
        for (int j = 0; j < 8; j++) {
            float2 f = u2f(acc2[i >> 1][j]);
            av[j] = (i & 1) ? f.y : f.x;
        }
        float4 r0, r1;
        r0.x = av[0] + bo[n0 + tn * 8 + 0];
        r0.y = av[1] + bo[n0 + tn * 8 + 1];
        r0.z = av[2] + bo[n0 + tn * 8 + 2];
        r0.w = av[3] + bo[n0 + tn * 8 + 3];
        r1.x = av[4] + bo[n0 + tn * 8 + 4];
        r1.y = av[5] + bo[n0 + tn * 8 + 5];
        r1.z = av[6] + bo[n0 + tn * 8 + 6];
        r1.w = av[7] + bo[n0 + tn * 8 + 7];
        *(float4*)&out[(size_t)m * kD + n0 + tn * 8] = r0;
        *(float4*)&out[(size_t)m * kD + n0 + tn * 8 + 4] = r1;
    }
}

// ---------------------------------------------------------------------------
// Launch
// Inputs: x, mask, rotary_freqs, past_k, past_v, Wq, bq, Wk, bk, Wv, bv, Wo, bo
// ---------------------------------------------------------------------------
extern "C" void kernel_launch(void* const* d_in, const int* in_sizes, int n_in,
                              void* d_out, int out_size) {
    const float* x  = (const float*)d_in[0];
    const float* rf = (const float*)d_in[2];
    const float* pk = (const float*)d_in[3];
    const float* pv = (const float*)d_in[4];
    const float* Wq = (const float*)d_in[5];
    const float* bq = (const float*)d_in[6];
    const float* Wk = (const float*)d_in[7];
    const float* bk = (const float*)d_in[8];
    const float* Wv = (const float*)d_in[9];
    const float* bv = (const float*)d_in[10];
    const float* Wo = (const float*)d_in[11];
    const float* bo = (const float*)d_in[12];
    float* out = (float*)d_out;

    cudaFuncSetAttribute(attn_kernel,
                         cudaFuncAttributeMaxDynamicSharedMemorySize,
                         ATTN_SMEM_BYTES);

    copy_past_kernel<<<2048, 256>>>((const float4*)pk, (const float4*)pv);
    qkv_kernel<<<dim3(kNTOT / 128, kM / 128), 256>>>(x, rf, Wq, bq, Wk, bk, Wv, bv);
    attn_kernel<<<dim3(kLQ / 128, kH, kB), 256, ATTN_SMEM_BYTES>>>();
    out_kernel<<<dim3(kD / 128, kM / 128), 256>>>(Wo, bo, out);
}

// round 3
// speedup vs baseline: 3.7321x; 2.4464x over previous
#include <cuda_runtime.h>
#include <math.h>
#include <stdint.h>

// Problem constants
namespace {
constexpr int kB    = 4;
constexpr int kLQ   = 1024;
constexpr int kD    = 2048;
constexpr int kH    = 16;
constexpr int kG    = 4;
constexpr int kHD   = 128;
constexpr int kPAST = 1024;
constexpr int kLK   = 2048;
constexpr int kM    = kB * kLQ;          // 4096
constexpr int kNQ   = kD;                // 2048
constexpr int kNKV  = kG * kHD;          // 512
constexpr int kNTOT = kNQ + 2 * kNKV;    // 3072
constexpr float kScale = 0.08838834764831845f; // 1/sqrt(128)
}

// Scratch
__device__ float g_q  [kB * kH * kLQ * kHD];
__device__ float g_kc [kB * kG * kLK * kHD];
__device__ float g_vc [kB * kG * kLK * kHD];
__device__ float g_att[kB * kLQ * kD];

// ---------------------------------------------------------------------------
// tf32 helpers
// ---------------------------------------------------------------------------
__device__ __forceinline__ uint32_t f2tf(float f) {
    uint32_t r;
    asm("cvt.rna.tf32.f32 %0, %1;" : "=r"(r) : "f"(f));
    return r;
}
__device__ __forceinline__ void mma_tf32(float* c, const uint32_t* a, const uint32_t* b) {
    asm volatile(
        "mma.sync.aligned.m16n8k8.row.col.f32.tf32.tf32.f32 "
        "{%0,%1,%2,%3}, {%4,%5,%6,%7}, {%8,%9}, {%0,%1,%2,%3};"
        : "+f"(c[0]), "+f"(c[1]), "+f"(c[2]), "+f"(c[3])
        : "r"(a[0]), "r"(a[1]), "r"(a[2]), "r"(a[3]), "r"(b[0]), "r"(b[1]));
}
__device__ __forceinline__ uint4 cvt4(float4 v) {
    return make_uint4(f2tf(v.x), f2tf(v.y), f2tf(v.z), f2tf(v.w));
}
__device__ __forceinline__ uint4 cvt4s(float4 v, float s) {
    return make_uint4(f2tf(v.x * s), f2tf(v.y * s), f2tf(v.z * s), f2tf(v.w * s));
}

// ---------------------------------------------------------------------------
// Kernel 1: copy past_k/past_v into caches
// ---------------------------------------------------------------------------
__global__ void copy_past_kernel(const float4* __restrict__ pk,
                                 const float4* __restrict__ pv) {
    constexpr int chunk4 = kPAST * kHD / 4;
    constexpr int dst4   = kLK * kHD / 4;
    constexpr int total4 = kB * kG * chunk4;
    int i = blockIdx.x * blockDim.x + threadIdx.x;
    if (i < total4) {
        int cg  = i / chunk4;
        int rem = i - cg * chunk4;
        ((float4*)g_kc)[cg * dst4 + rem] = pk[i];
        ((float4*)g_vc)[cg * dst4 + rem] = pv[i];
    }
}

// ---------------------------------------------------------------------------
// Kernel 2: QKV projection, tf32 HMMA, 128x128x32 tile, 8 warps (64x32 each)
// ---------------------------------------------------------------------------
constexpr int AS_ST = 36;    // As[m][k], stride%32==4 -> a-frag conflict-free
constexpr int BS_ST = 136;   // Bs[k][n], stride%32==8 -> b-frag conflict-free

__global__ __launch_bounds__(256, 1) void qkv_kernel(
    const float* __restrict__ x,  const float* __restrict__ rf,
    const float* __restrict__ Wq, const float* __restrict__ bq,
    const float* __restrict__ Wk, const float* __restrict__ bk,
    const float* __restrict__ Wv, const float* __restrict__ bv) {

    __shared__ uint32_t As[128 * AS_ST];
    __shared__ uint32_t Bs[32 * BS_ST];

    const int n0  = blockIdx.x * 128;
    const int m0  = blockIdx.y * 128;
    const int tid = threadIdx.x;
    const int wid = tid >> 5, lane = tid & 31;
    const int wm = (wid >> 2) * 64;      // 0 / 64
    const int wn = (wid & 3) * 32;       // 0..96
    const int ln4 = lane >> 2, lc4 = lane & 3;

    const float* W; const float* bias; int nloc; int Nw; int seg;
    if (n0 < kNQ)              { W = Wq; bias = bq; nloc = n0;              Nw = kNQ;  seg = 0; }
    else if (n0 < kNQ + kNKV)  { W = Wk; bias = bk; nloc = n0 - kNQ;        Nw = kNKV; seg = 1; }
    else                       { W = Wv; bias = bv; nloc = n0 - kNQ - kNKV; Nw = kNKV; seg = 2; }

    float acc[4][4][4] = {};

    for (int k0 = 0; k0 < kD; k0 += 32) {
#pragma unroll
        for (int it = 0; it < 4; it++) {           // A: 128x32
            int idx = tid + it * 256;
            int m = idx >> 3, kq = idx & 7;
            float4 v = *(const float4*)&x[(size_t)(m0 + m) * kD + k0 + kq * 4];
            *(uint4*)&As[m * AS_ST + kq * 4] = cvt4(v);
        }
#pragma unroll
        for (int it = 0; it < 4; it++) {           // B: 32x128
            int idx = tid + it * 256;
            int kk = idx >> 5, nq = idx & 31;
            float4 v = *(const float4*)&W[(size_t)(k0 + kk) * Nw + nloc + nq * 4];
            *(uint4*)&Bs[kk * BS_ST + nq * 4] = cvt4(v);
        }
        __syncthreads();
#pragma unroll
        for (int k8 = 0; k8 < 32; k8 += 8) {
            uint32_t a[4][4];
#pragma unroll
            for (int mf = 0; mf < 4; mf++) {
                int base = (wm + mf * 16 + ln4) * AS_ST + k8 + lc4;
                a[mf][0] = As[base];
                a[mf][1] = As[base + 8 * AS_ST];
                a[mf][2] = As[base + 4];
                a[mf][3] = As[base + 8 * AS_ST + 4];
            }
            uint32_t b[4][2];
#pragma unroll
            for (int nf = 0; nf < 4; nf++) {
                int base = (k8 + lc4) * BS_ST + wn + nf * 8 + ln4;
                b[nf][0] = Bs[base];
                b[nf][1] = Bs[base + 4 * BS_ST];
            }
#pragma unroll
            for (int mf = 0; mf < 4; mf++)
#pragma unroll
                for (int nf = 0; nf < 4; nf++)
                    mma_tf32(acc[mf][nf], a[mf], b[nf]);
        }
        __syncthreads();
    }

    // Epilogue: bias + RoPE + scatter
#pragma unroll
    for (int mf = 0; mf < 4; mf++) {
#pragma unroll
        for (int rp = 0; rp < 2; rp++) {
            const int m = m0 + wm + mf * 16 + ln4 + rp * 8;
            const int b = m >> 10;
            const int t = m & (kLQ - 1);
#pragma unroll
            for (int nf = 0; nf < 4; nf++) {
                const int n = nloc + wn + nf * 8 + lc4 * 2;
                float v0 = acc[mf][nf][rp * 2 + 0] + bias[n];
                float v1 = acc[mf][nf][rp * 2 + 1] + bias[n + 1];
                const int d = n & 127;
                if (seg == 0) {
                    const int h = n >> 7;
                    float sn, cs; sincosf(rf[t * (kHD / 2) + (d >> 1)], &sn, &cs);
                    float r0 = v0 * cs - v1 * sn;
                    float r1 = v0 * sn + v1 * cs;
                    float* dst = &g_q[((size_t)((b * kH + h) * kLQ + t) * kHD) + d];
                    dst[0] = r0; dst[1] = r1;
                } else if (seg == 1) {
                    const int g = n >> 7;
                    float sn, cs; sincosf(rf[t * (kHD / 2) + (d >> 1)], &sn, &cs);
                    float r0 = v0 * cs - v1 * sn;
                    float r1 = v0 * sn + v1 * cs;
                    float* dst = &g_kc[((size_t)((b * kG + g) * kLK + kPAST + t) * kHD) + d];
                    dst[0] = r0; dst[1] = r1;
                } else {
                    const int g = n >> 7;
                    float* dst = &g_vc[((size_t)((b * kG + g) * kLK + kPAST + t) * kHD) + d];
                    dst[0] = v0; dst[1] = v1;
                }
            }
        }
    }
}

// ---------------------------------------------------------------------------
// Kernel 3: flash attention, tf32 HMMA. BQ=128, BK=64, 8 warps x 16 q-rows.
// ---------------------------------------------------------------------------
constexpr int QS_ST = 132;   // Qs[t][d]   %32==4 -> a-frag CF
constexpr int KR_ST = 132;   // Kr[key][d] %32==4 -> b-frag CF (read [n][k])
constexpr int VS_ST = 136;   // Vs[key][d] %32==8 -> b-frag CF (read [k][n])
constexpr int PS_ST = 68;    // Ps[q][key] %32==4 -> a-frag CF
constexpr int ATTN_WORDS = 128 * QS_ST + 64 * KR_ST + 64 * VS_ST + 128 * PS_ST;
constexpr int ATTN_SMEM_BYTES = ATTN_WORDS * 4;   // 171,008 B

__global__ __launch_bounds__(256, 1) void attn_kernel() {
    extern __shared__ uint32_t smw[];
    uint32_t* Qs = smw;
    uint32_t* Kr = Qs + 128 * QS_ST;
    uint32_t* Vs = Kr + 64 * KR_ST;
    uint32_t* Ps = Vs + 64 * VS_ST;

    const int qb = blockIdx.x;
    const int h  = blockIdx.y;
    const int b  = blockIdx.z;
    const int g  = h >> 2;
    const int t0 = qb * 128;
    const int tid = threadIdx.x;
    const int wid = tid >> 5, lane = tid & 31;
    const int rq = wid * 16;                 // warp's q-row base
    const int ln4 = lane >> 2, lc4 = lane & 3;

    // Load Q (pre-scaled, tf32)
    const float* qbase = g_q + ((size_t)(b * kH + h) * kLQ + t0) * kHD;
#pragma unroll
    for (int it = 0; it < 16; it++) {
        int idx = tid + it * 256;
        int t = idx >> 5, d4 = (idx & 31) * 4;
        float4 v = *(const float4*)&qbase[(size_t)t * kHD + d4];
        *(uint4*)&Qs[t * QS_ST + d4] = cvt4s(v, kScale);
    }

    float oacc[16][4] = {};
    float mA = -1e30f, lA = 0.f, mB = -1e30f, lB = 0.f;

    const float* kbase = g_kc + (size_t)(b * kG + g) * kLK * kHD;
    const float* vbase = g_vc + (size_t)(b * kG + g) * kLK * kHD;
    const int ntiles = (kPAST + t0 + 128) / 64;

    for (int kt = 0; kt < ntiles; kt++) {
        const int k0 = kt * 64;
        __syncthreads();
#pragma unroll
        for (int it = 0; it < 8; it++) {
            int idx = tid + it * 256;
            int key = idx >> 5, d4 = (idx & 31) * 4;
            float4 kv = *(const float4*)&kbase[(size_t)(k0 + key) * kHD + d4];
            float4 vv = *(const float4*)&vbase[(size_t)(k0 + key) * kHD + d4];
            *(uint4*)&Kr[key * KR_ST + d4] = cvt4(kv);
            *(uint4*)&Vs[key * VS_ST + d4] = cvt4(vv);
        }
        __syncthreads();

        // S = Q.K^T  (warp: m16 x n64, k=128)
        float sacc[8][4] = {};
#pragma unroll
        for (int k8 = 0; k8 < 16; k8++) {
            const int d0 = k8 * 8;
            uint32_t a[4];
            int qb_ = (rq + ln4) * QS_ST + d0 + lc4;
            a[0] = Qs[qb_];
            a[1] = Qs[qb_ + 8 * QS_ST];
            a[2] = Qs[qb_ + 4];
            a[3] = Qs[qb_ + 8 * QS_ST + 4];
#pragma unroll
            for (int nf = 0; nf < 8; nf++) {
                uint32_t bfr[2];
                int kb_ = (nf * 8 + ln4) * KR_ST + d0 + lc4;
                bfr[0] = Kr[kb_];
                bfr[1] = Kr[kb_ + 4];
                mma_tf32(sacc[nf], a, bfr);
            }
        }

        // causal mask (only near the diagonal)
        const int qposA = kPAST + t0 + rq + ln4;
        if (k0 + 63 > kPAST + t0) {
#pragma unroll
            for (int nf = 0; nf < 8; nf++) {
#pragma unroll
                for (int j = 0; j < 2; j++) {
                    int kpos = k0 + nf * 8 + lc4 * 2 + j;
                    if (kpos > qposA)     sacc[nf][j]     = -1e30f;
                    if (kpos > qposA + 8) sacc[nf][2 + j] = -1e30f;
                }
            }
        }

        // online softmax: two rows per thread (rq+ln4, rq+ln4+8)
        float mxA = -1e30f, mxB = -1e30f;
#pragma unroll
        for (int nf = 0; nf < 8; nf++) {
            mxA = fmaxf(mxA, fmaxf(sacc[nf][0], sacc[nf][1]));
            mxB = fmaxf(mxB, fmaxf(sacc[nf][2], sacc[nf][3]));
        }
#pragma unroll
        for (int off = 1; off < 4; off <<= 1) {
            mxA = fmaxf(mxA, __shfl_xor_sync(0xffffffffu, mxA, off));
            mxB = fmaxf(mxB, __shfl_xor_sync(0xffffffffu, mxB, off));
        }
        float mnA = fmaxf(mA, mxA), mnB = fmaxf(mB, mxB);
        float alA = __expf(mA - mnA), alB = __expf(mB - mnB);
        float sumA = 0.f, sumB = 0.f;
#pragma unroll
        for (int nf = 0; nf < 8; nf++) {
            float p0 = __expf(sacc[nf][0] - mnA);
            float p1 = __expf(sacc[nf][1] - mnA);
            float p2 = __expf(sacc[nf][2] - mnB);
            float p3 = __expf(sacc[nf][3] - mnB);
            sumA += p0 + p1; sumB += p2 + p3;
            int pc = nf * 8 + lc4 * 2;
            *(uint2*)&Ps[(rq + ln4) * PS_ST + pc]     = make_uint2(f2tf(p0), f2tf(p1));
            *(uint2*)&Ps[(rq + ln4 + 8) * PS_ST + pc] = make_uint2(f2tf(p2), f2tf(p3));
        }
#pragma unroll
        for (int off = 1; off < 4; off <<= 1) {
            sumA += __shfl_xor_sync(0xffffffffu, sumA, off);
            sumB += __shfl_xor_sync(0xffffffffu, sumB, off);
        }
        lA = lA * alA + sumA;  mA = mnA;
        lB = lB * alB + sumB;  mB = mnB;

        // rescale O
#pragma unroll
        for (int nf = 0; nf < 16; nf++) {
            oacc[nf][0] *= alA; oacc[nf][1] *= alA;
            oacc[nf][2] *= alB; oacc[nf][3] *= alB;
        }
        __syncwarp();

        // O += P.V  (warp: m16 x n128, k=64)
#pragma unroll
        for (int kk8 = 0; kk8 < 8; kk8++) {
            const int kk0 = kk8 * 8;
            uint32_t a[4];
            int pb_ = (rq + ln4) * PS_ST + kk0 + lc4;
            a[0] = Ps[pb_];
            a[1] = Ps[pb_ + 8 * PS_ST];
            a[2] = Ps[pb_ + 4];
            a[3] = Ps[pb_ + 8 * PS_ST + 4];
#pragma unroll
            for (int nf = 0; nf < 16; nf++) {
                uint32_t bfr[2];
                int vb_ = (kk0 + lc4) * VS_ST + nf * 8 + ln4;
                bfr[0] = Vs[vb_];
                bfr[1] = Vs[vb_ + 4 * VS_ST];
                mma_tf32(oacc[nf], a, bfr);
            }
        }
    }

    // Normalize + store
    const float invA = 1.f / lA, invB = 1.f / lB;
    const int tA = t0 + rq + ln4;
    float* dA = &g_att[((size_t)(b * kLQ + tA)) * kD + h * kHD];
    float* dB = &g_att[((size_t)(b * kLQ + tA + 8)) * kD + h * kHD];
#pragma unroll
    for (int nf = 0; nf < 16; nf++) {
        int col = nf * 8 + lc4 * 2;
        *(float2*)&dA[col] = make_float2(oacc[nf][0] * invA, oacc[nf][1] * invA);
        *(float2*)&dB[col] = make_float2(oacc[nf][2] * invB, oacc[nf][3] * invB);
    }
}

// ---------------------------------------------------------------------------
// Kernel 4: output GEMM, tf32 HMMA, 128x128x32
// ---------------------------------------------------------------------------
__global__ __launch_bounds__(256, 1) void out_kernel(
    const float* __restrict__ Wo, const float* __restrict__ bo,
    float* __restrict__ out) {

    __shared__ uint32_t As[128 * AS_ST];
    __shared__ uint32_t Bs[32 * BS_ST];

    const int n0  = blockIdx.x * 128;
    const int m0  = blockIdx.y * 128;
    const int tid = threadIdx.x;
    const int wid = tid >> 5, lane = tid & 31;
    const int wm = (wid >> 2) * 64;
    const int wn = (wid & 3) * 32;
    const int ln4 = lane >> 2, lc4 = lane & 3;

    float acc[4][4][4] = {};

    for (int k0 = 0; k0 < kD; k0 += 32) {
#pragma unroll
        for (int it = 0; it < 4; it++) {
            int idx = tid + it * 256;
            int m = idx >> 3, kq = idx & 7;
            float4 v = *(const float4*)&g_att[(size_t)(m0 + m) * kD + k0 + kq * 4];
            *(uint4*)&As[m * AS_ST + kq * 4] = cvt4(v);
        }
#pragma unroll
        for (int it = 0; it < 4; it++) {
            int idx = tid + it * 256;
            int kk = idx >> 5, nq = idx & 31;
            float4 v = *(const float4*)&Wo[(size_t)(k0 + kk) * kD + n0 + nq * 4];
            *(uint4*)&Bs[kk * BS_ST + nq * 4] = cvt4(v);
        }
        __syncthreads();
#pragma unroll
        for (int k8 = 0; k8 < 32; k8 += 8) {
            uint32_t a[4][4];
#pragma unroll
            for (int mf = 0; mf < 4; mf++) {
                int base = (wm + mf * 16 + ln4) * AS_ST + k8 + lc4;
                a[mf][0] = As[base];
                a[mf][1] = As[base + 8 * AS_ST];
                a[mf][2] = As[base + 4];
                a[mf][3] = As[base + 8 * AS_ST + 4];
            }
            uint32_t b[4][2];
#pragma unroll
            for (int nf = 0; nf < 4; nf++) {
                int base = (k8 + lc4) * BS_ST + wn + nf * 8 + ln4;
                b[nf][0] = Bs[base];
                b[nf][1] = Bs[base + 4 * BS_ST];
            }
#pragma unroll
            for (int mf = 0; mf < 4; mf++)
#pragma unroll
                for (int nf = 0; nf < 4; nf++)
                    mma_tf32(acc[mf][nf], a[mf], b[nf]);
        }
        __syncthreads();
    }

#pragma unroll
    for (int mf = 0; mf < 4; mf++) {
#pragma unroll
        for (int rp = 0; rp < 2; rp++) {
            const int m = m0 + wm + mf * 16 + ln4 + rp * 8;
#pragma unroll
            for (int nf = 0; nf < 4; nf++) {
                const int n = n0 + wn + nf * 8 + lc4 * 2;
                float v0 = acc[mf][nf][rp * 2 + 0] + bo[n];
                float v1 = acc[mf][nf][rp * 2 + 1] + bo[n + 1];
                *(float2*)&out[(size_t)m * kD + n] = make_float2(v0, v1);
            }
        }
    }
}

// ---------------------------------------------------------------------------
// Launch
// ---------------------------------------------------------------------------
extern "C" void kernel_launch(void* const* d_in, const int* in_sizes, int n_in,
                              void* d_out, int out_size) {
    const float* x  = (const float*)d_in[0];
    const float* rf = (const float*)d_in[2];
    const float* pk = (const float*)d_in[3];
    const float* pv = (const float*)d_in[4];
    const float* Wq = (const float*)d_in[5];
    const float* bq = (const float*)d_in[6];
    const float* Wk = (const float*)d_in[7];
    const float* bk = (const float*)d_in[8];
    const float* Wv = (const float*)d_in[9];
    const float* bv = (const float*)d_in[10];
    const float* Wo = (const float*)d_in[11];
    const float* bo = (const float*)d_in[12];
    float* out = (float*)d_out;

    cudaFuncSetAttribute(attn_kernel,
                         cudaFuncAttributeMaxDynamicSharedMemorySize,
                         ATTN_SMEM_BYTES);

    copy_past_kernel<<<2048, 256>>>((const float4*)pk, (const float4*)pv);
    qkv_kernel<<<dim3(kNTOT / 128, kM / 128), 256>>>(x, rf, Wq, bq, Wk, bk, Wv, bv);
    attn_kernel<<<dim3(kLQ / 128, kH, kB), 256, ATTN_SMEM_BYTES>>>();
    out_kernel<<<dim3(kD / 128, kM / 128), 256>>>(Wo, bo, out);
}

// round 5
// speedup vs baseline: 4.4894x; 1.2029x over previous
#include <cuda_runtime.h>
#include <math.h>
#include <stdint.h>

// Problem constants
namespace {
constexpr int kB    = 4;
constexpr int kLQ   = 1024;
constexpr int kD    = 2048;
constexpr int kH    = 16;
constexpr int kG    = 4;
constexpr int kHD   = 128;
constexpr int kPAST = 1024;
constexpr int kLK   = 2048;
constexpr int kM    = kB * kLQ;          // 4096
constexpr int kNQ   = kD;                // 2048
constexpr int kNKV  = kG * kHD;          // 512
constexpr int kNTOT = kNQ + 2 * kNKV;    // 3072
constexpr float kScale = 0.08838834764831845f; // 1/sqrt(128)
}

// Scratch: all hold tf32 bit patterns (pre-converted by producers)
__device__ uint32_t g_q  [kB * kH * kLQ * kHD];   // pre-scaled by kScale
__device__ uint32_t g_kc [kB * kG * kLK * kHD];
__device__ uint32_t g_vc [kB * kG * kLK * kHD];
__device__ uint32_t g_att[kB * kLQ * kD];

// ---------------------------------------------------------------------------
// helpers
// ---------------------------------------------------------------------------
__device__ __forceinline__ uint32_t f2tf(float f) {
    uint32_t r;
    asm("cvt.rna.tf32.f32 %0, %1;" : "=r"(r) : "f"(f));
    return r;
}
__device__ __forceinline__ void mma_tf32(float* c, const uint32_t* a, const uint32_t* b) {
    asm volatile(
        "mma.sync.aligned.m16n8k8.row.col.f32.tf32.tf32.f32 "
        "{%0,%1,%2,%3}, {%4,%5,%6,%7}, {%8,%9}, {%0,%1,%2,%3};"
        : "+f"(c[0]), "+f"(c[1]), "+f"(c[2]), "+f"(c[3])
        : "r"(a[0]), "r"(a[1]), "r"(a[2]), "r"(a[3]), "r"(b[0]), "r"(b[1]));
}
__device__ __forceinline__ uint4 cvt4(float4 v) {
    return make_uint4(f2tf(v.x), f2tf(v.y), f2tf(v.z), f2tf(v.w));
}
__device__ __forceinline__ uint32_t s2u(const void* p) {
    return (uint32_t)__cvta_generic_to_shared(p);
}
__device__ __forceinline__ void cp16(uint32_t saddr, const void* gptr) {
    asm volatile("cp.async.cg.shared.global [%0], [%1], 16;"
                 :: "r"(saddr), "l"(gptr));
}
__device__ __forceinline__ void cp_commit() {
    asm volatile("cp.async.commit_group;" ::: "memory");
}
template <int N>
__device__ __forceinline__ void cp_wait() {
    asm volatile("cp.async.wait_group %0;" :: "n"(N) : "memory");
}

// ---------------------------------------------------------------------------
// Kernel 1: copy past_k/past_v into caches (convert to tf32)
// ---------------------------------------------------------------------------
__global__ void copy_past_kernel(const float4* __restrict__ pk,
                                 const float4* __restrict__ pv) {
    constexpr int chunk4 = kPAST * kHD / 4;
    constexpr int dst4   = kLK * kHD / 4;
    constexpr int total4 = kB * kG * chunk4;
    int i = blockIdx.x * blockDim.x + threadIdx.x;
    if (i < total4) {
        int cg  = i / chunk4;
        int rem = i - cg * chunk4;
        ((uint4*)g_kc)[cg * dst4 + rem] = cvt4(pk[i]);
        ((uint4*)g_vc)[cg * dst4 + rem] = cvt4(pv[i]);
    }
}

// ---------------------------------------------------------------------------
// GEMM pipeline constants (qkv + out): 128x128x32, 3-stage cp.async
// ---------------------------------------------------------------------------
constexpr int A_ST  = 36;    // As[m][k] stride (%32==4 -> a-frag CF)
constexpr int B_ST  = 136;   // Bs[k][n] stride (%32==8 -> b-frag CF)
constexpr int STG_A = 128 * A_ST;   // 4608 words
constexpr int STG_B = 32 * B_ST;    // 4352 words
constexpr int STG_W = STG_A + STG_B;
constexpr int NSTG  = 3;
constexpr int GEMM_SMEM = NSTG * STG_W * 4;   // 107,520 B

// ---------------------------------------------------------------------------
// Kernel 2: QKV projection GEMM + bias + RoPE + tf32 scatter
// ---------------------------------------------------------------------------
__global__ __launch_bounds__(256, 1) void qkv_kernel(
    const float* __restrict__ x,  const float* __restrict__ rf,
    const float* __restrict__ Wq, const float* __restrict__ bq,
    const float* __restrict__ Wk, const float* __restrict__ bk,
    const float* __restrict__ Wv, const float* __restrict__ bv) {

    extern __shared__ float smf[];

    const int n0  = blockIdx.x * 128;
    const int m0  = blockIdx.y * 128;
    const int tid = threadIdx.x;
    const int wid = tid >> 5, lane = tid & 31;
    const int wm = (wid >> 2) * 64;
    const int wn = (wid & 3) * 32;
    const int ln4 = lane >> 2, lc4 = lane & 3;

    const float* W; const float* bias; int nloc; int Nw; int seg;
    if (n0 < kNQ)              { W = Wq; bias = bq; nloc = n0;              Nw = kNQ;  seg = 0; }
    else if (n0 < kNQ + kNKV)  { W = Wk; bias = bk; nloc = n0 - kNQ;        Nw = kNKV; seg = 1; }
    else                       { W = Wv; bias = bv; nloc = n0 - kNQ - kNKV; Nw = kNKV; seg = 2; }

    auto load_stage = [&](int s, int k0) {
        float* As = smf + s * STG_W;
        float* Bs = As + STG_A;
#pragma unroll
        for (int it = 0; it < 4; it++) {        // A: 128 rows x 8 float4 (BK=32)
            int idx = tid + it * 256;
            int m = idx >> 3, q = idx & 7;
            cp16(s2u(&As[m * A_ST + q * 4]),
                 &x[(size_t)(m0 + m) * kD + k0 + q * 4]);
        }
#pragma unroll
        for (int it = 0; it < 4; it++) {        // B: 32 rows x 32 float4 (BN=128)
            int idx = tid + it * 256;
            int kk = idx >> 5, nq = idx & 31;
            cp16(s2u(&Bs[kk * B_ST + nq * 4]),
                 &W[(size_t)(k0 + kk) * Nw + nloc + nq * 4]);
        }
    };

    float acc[4][4][4] = {};

#pragma unroll
    for (int s = 0; s < NSTG; s++) { load_stage(s, s * 32); cp_commit(); }

    const int KT = kD / 32;
    for (int ki = 0; ki < KT; ki++) {
        cp_wait<NSTG - 1>();
        __syncthreads();
        const float* As = smf + (ki % NSTG) * STG_W;
        const float* Bs = As + STG_A;
#pragma unroll
        for (int k8 = 0; k8 < 32; k8 += 8) {
            uint32_t a[4][4];
#pragma unroll
            for (int mf = 0; mf < 4; mf++) {
                int base = (wm + mf * 16 + ln4) * A_ST + k8 + lc4;
                a[mf][0] = f2tf(As[base]);
                a[mf][1] = f2tf(As[base + 8 * A_ST]);
                a[mf][2] = f2tf(As[base + 4]);
                a[mf][3] = f2tf(As[base + 8 * A_ST + 4]);
            }
            uint32_t bb[4][2];
#pragma unroll
            for (int nf = 0; nf < 4; nf++) {
                int base = (k8 + lc4) * B_ST + wn + nf * 8 + ln4;
                bb[nf][0] = f2tf(Bs[base]);
                bb[nf][1] = f2tf(Bs[base + 4 * B_ST]);
            }
#pragma unroll
            for (int mf = 0; mf < 4; mf++)
#pragma unroll
                for (int nf = 0; nf < 4; nf++)
                    mma_tf32(acc[mf][nf], a[mf], bb[nf]);
        }
        __syncthreads();
        int kn = ki + NSTG;
        if (kn < KT) load_stage(ki % NSTG, kn * 32);
        cp_commit();
    }

    // Epilogue: bias + RoPE + tf32 scatter
#pragma unroll
    for (int mf = 0; mf < 4; mf++) {
#pragma unroll
        for (int rp = 0; rp < 2; rp++) {
            const int m = m0 + wm + mf * 16 + ln4 + rp * 8;
            const int b = m >> 10;
            const int t = m & (kLQ - 1);
#pragma unroll
            for (int nf = 0; nf < 4; nf++) {
                const int n = nloc + wn + nf * 8 + lc4 * 2;
                float v0 = acc[mf][nf][rp * 2 + 0] + bias[n];
                float v1 = acc[mf][nf][rp * 2 + 1] + bias[n + 1];
                const int d = n & 127;
                if (seg == 0) {
                    const int h = n >> 7;
                    float sn, cs; sincosf(rf[t * (kHD / 2) + (d >> 1)], &sn, &cs);
                    float r0 = v0 * cs - v1 * sn;
                    float r1 = v0 * sn + v1 * cs;
                    uint32_t* dst = &g_q[((size_t)((b * kH + h) * kLQ + t) * kHD) + d];
                    *(uint2*)dst = make_uint2(f2tf(r0 * kScale), f2tf(r1 * kScale));
                } else if (seg == 1) {
                    const int g = n >> 7;
                    float sn, cs; sincosf(rf[t * (kHD / 2) + (d >> 1)], &sn, &cs);
                    float r0 = v0 * cs - v1 * sn;
                    float r1 = v0 * sn + v1 * cs;
                    uint32_t* dst = &g_kc[((size_t)((b * kG + g) * kLK + kPAST + t) * kHD) + d];
                    *(uint2*)dst = make_uint2(f2tf(r0), f2tf(r1));
                } else {
                    const int g = n >> 7;
                    uint32_t* dst = &g_vc[((size_t)((b * kG + g) * kLK + kPAST + t) * kHD) + d];
                    *(uint2*)dst = make_uint2(f2tf(v0), f2tf(v1));
                }
            }
        }
    }
}

// ---------------------------------------------------------------------------
// Kernel 3: flash attention, tf32 HMMA, ping-pong K/V cp.async.
// BQ=128, BK=64, 8 warps x 16 q-rows.
// ---------------------------------------------------------------------------
constexpr int QS_ST = 132;   // %32==4 -> a-frag CF
constexpr int KK_ST = 132;   // %32==4 -> b-frag CF ([n][k] reads)
constexpr int VV_ST = 136;   // %32==8 -> b-frag CF ([k][n] reads)
constexpr int PS_ST = 68;    // %32==4 -> a-frag CF
constexpr int ATTN_WORDS = 128 * QS_ST + 64 * KK_ST + 64 * VV_ST + 128 * PS_ST;
constexpr int ATTN_SMEM_BYTES = ATTN_WORDS * 4;   // 171,008 B

__global__ __launch_bounds__(256, 1) void attn_kernel() {
    extern __shared__ uint32_t smw[];
    uint32_t* Qs = smw;
    uint32_t* Kb = Qs + 128 * QS_ST;
    uint32_t* Vb = Kb + 64 * KK_ST;
    uint32_t* Ps = Vb + 64 * VV_ST;

    const int qb = blockIdx.x;
    const int h  = blockIdx.y;
    const int b  = blockIdx.z;
    const int g  = h >> 2;
    const int t0 = qb * 128;
    const int tid = threadIdx.x;
    const int wid = tid >> 5, lane = tid & 31;
    const int rq = wid * 16;
    const int ln4 = lane >> 2, lc4 = lane & 3;

    const uint32_t* qbase = g_q  + ((size_t)(b * kH + h) * kLQ + t0) * kHD;
    const uint32_t* kbase = g_kc + (size_t)(b * kG + g) * kLK * kHD;
    const uint32_t* vbase = g_vc + (size_t)(b * kG + g) * kLK * kHD;

    // Prologue group 0: Q tile (128 rows x 32 float4) + K(0) (64 rows x 32 float4)
#pragma unroll
    for (int it = 0; it < 16; it++) {
        int idx = tid + it * 256;
        int t = idx >> 5, q = idx & 31;
        cp16(s2u(&Qs[t * QS_ST + q * 4]), &qbase[(size_t)t * kHD + q * 4]);
    }
#pragma unroll
    for (int it = 0; it < 8; it++) {
        int idx = tid + it * 256;
        int key = idx >> 5, q = idx & 31;
        cp16(s2u(&Kb[key * KK_ST + q * 4]), &kbase[(size_t)key * kHD + q * 4]);
    }
    cp_commit();

    float oacc[16][4] = {};
    float mA = -1e30f, lA = 0.f, mB = -1e30f, lB = 0.f;
    const int ntiles = (kPAST + t0) / 64 + 2;

    for (int kt = 0; kt < ntiles; kt++) {
        const int k0 = kt * 64;
        cp_wait<0>();          // K(kt) (+Q on first iter) resident
        __syncthreads();       // fences previous O-mma reads of Vb

        // stream V(kt) during S-phase (64 rows x 32 float4)
#pragma unroll
        for (int it = 0; it < 8; it++) {
            int idx = tid + it * 256;
            int key = idx >> 5, q = idx & 31;
            cp16(s2u(&Vb[key * VV_ST + q * 4]),
                 &vbase[(size_t)(k0 + key) * kHD + q * 4]);
        }
        cp_commit();

        // S = Q.K^T  (warp: m16 x n64, k=128)
        float sacc[8][4] = {};
#pragma unroll
        for (int k8 = 0; k8 < 16; k8++) {
            const int d0 = k8 * 8;
            uint32_t a[4];
            int qb_ = (rq + ln4) * QS_ST + d0 + lc4;
            a[0] = Qs[qb_];
            a[1] = Qs[qb_ + 8 * QS_ST];
            a[2] = Qs[qb_ + 4];
            a[3] = Qs[qb_ + 8 * QS_ST + 4];
#pragma unroll
            for (int nf = 0; nf < 8; nf++) {
                uint32_t bfr[2];
                int kb_ = (nf * 8 + ln4) * KK_ST + d0 + lc4;
                bfr[0] = Kb[kb_];
                bfr[1] = Kb[kb_ + 4];
                mma_tf32(sacc[nf], a, bfr);
            }
        }

        // causal mask near diagonal
        const int qposA = kPAST + t0 + rq + ln4;
        if (k0 + 63 > kPAST + t0) {
#pragma unroll
            for (int nf = 0; nf < 8; nf++) {
#pragma unroll
                for (int j = 0; j < 2; j++) {
                    int kpos = k0 + nf * 8 + lc4 * 2 + j;
                    if (kpos > qposA)     sacc[nf][j]     = -1e30f;
                    if (kpos > qposA + 8) sacc[nf][2 + j] = -1e30f;
                }
            }
        }

        // online softmax, rows rq+ln4 and rq+ln4+8
        float mxA = -1e30f, mxB = -1e30f;
#pragma unroll
        for (int nf = 0; nf < 8; nf++) {
            mxA = fmaxf(mxA, fmaxf(sacc[nf][0], sacc[nf][1]));
            mxB = fmaxf(mxB, fmaxf(sacc[nf][2], sacc[nf][3]));
        }
#pragma unroll
        for (int off = 1; off < 4; off <<= 1) {
            mxA = fmaxf(mxA, __shfl_xor_sync(0xffffffffu, mxA, off));
            mxB = fmaxf(mxB, __shfl_xor_sync(0xffffffffu, mxB, off));
        }
        float mnA = fmaxf(mA, mxA), mnB = fmaxf(mB, mxB);
        float alA = __expf(mA - mnA), alB = __expf(mB - mnB);
        float sumA = 0.f, sumB = 0.f;
#pragma unroll
        for (int nf = 0; nf < 8; nf++) {
            float p0 = __expf(sacc[nf][0] - mnA);
            float p1 = __expf(sacc[nf][1] - mnA);
            float p2 = __expf(sacc[nf][2] - mnB);
            float p3 = __expf(sacc[nf][3] - mnB);
            sumA += p0 + p1; sumB += p2 + p3;
            int pc = nf * 8 + lc4 * 2;
            *(uint2*)&Ps[(rq + ln4) * PS_ST + pc]     = make_uint2(f2tf(p0), f2tf(p1));
            *(uint2*)&Ps[(rq + ln4 + 8) * PS_ST + pc] = make_uint2(f2tf(p2), f2tf(p3));
        }
#pragma unroll
        for (int off = 1; off < 4; off <<= 1) {
            sumA += __shfl_xor_sync(0xffffffffu, sumA, off);
            sumB += __shfl_xor_sync(0xffffffffu, sumB, off);
        }
        lA = lA * alA + sumA;  mA = mnA;
        lB = lB * alB + sumB;  mB = mnB;

        // rescale O accumulators
#pragma unroll
        for (int nf = 0; nf < 16; nf++) {
            oacc[nf][0] *= alA; oacc[nf][1] *= alA;
            oacc[nf][2] *= alB; oacc[nf][3] *= alB;
        }
        __syncthreads();   // all warps done reading Kb

        // stream K(kt+1) during O-phase
        if (kt + 1 < ntiles) {
            int kn0 = k0 + 64;
#pragma unroll
            for (int it = 0; it < 8; it++) {
                int idx = tid + it * 256;
                int key = idx >> 5, q = idx & 31;
                cp16(s2u(&Kb[key * KK_ST + q * 4]),
                     &kbase[(size_t)(kn0 + key) * kHD + q * 4]);
            }
        }
        cp_commit();
        cp_wait<1>();      // V(kt) resident (K(kt+1) may still fly)
        __syncthreads();

        // O += P.V  (warp: m16 x n128, k=64)
#pragma unroll
        for (int kk8 = 0; kk8 < 8; kk8++) {
            const int kk0 = kk8 * 8;
            uint32_t a[4];
            int pb_ = (rq + ln4) * PS_ST + kk0 + lc4;
            a[0] = Ps[pb_];
            a[1] = Ps[pb_ + 8 * PS_ST];
            a[2] = Ps[pb_ + 4];
            a[3] = Ps[pb_ + 8 * PS_ST + 4];
#pragma unroll
            for (int nf = 0; nf < 16; nf++) {
                uint32_t bfr[2];
                int vb_ = (kk0 + lc4) * VV_ST + nf * 8 + ln4;
                bfr[0] = Vb[vb_];
                bfr[1] = Vb[vb_ + 4 * VV_ST];
                mma_tf32(oacc[nf], a, bfr);
            }
        }
    }

    // normalize + store tf32 to g_att
    const float invA = 1.f / lA, invB = 1.f / lB;
    const int tA = t0 + rq + ln4;
    uint32_t* dA = &g_att[((size_t)(b * kLQ + tA)) * kD + h * kHD];
    uint32_t* dB = &g_att[((size_t)(b * kLQ + tA + 8)) * kD + h * kHD];
#pragma unroll
    for (int nf = 0; nf < 16; nf++) {
        int col = nf * 8 + lc4 * 2;
        *(uint2*)&dA[col] = make_uint2(f2tf(oacc[nf][0] * invA), f2tf(oacc[nf][1] * invA));
        *(uint2*)&dB[col] = make_uint2(f2tf(oacc[nf][2] * invB), f2tf(oacc[nf][3] * invB));
    }
}

// ---------------------------------------------------------------------------
// Kernel 4: output GEMM (A = g_att tf32, B = Wo fp32), 3-stage pipeline
// ---------------------------------------------------------------------------
__global__ __launch_bounds__(256, 1) void out_kernel(
    const float* __restrict__ Wo, const float* __restrict__ bo,
    float* __restrict__ out) {

    extern __shared__ float smf[];

    const int n0  = blockIdx.x * 128;
    const int m0  = blockIdx.y * 128;
    const int tid = threadIdx.x;
    const int wid = tid >> 5, lane = tid & 31;
    const int wm = (wid >> 2) * 64;
    const int wn = (wid & 3) * 32;
    const int ln4 = lane >> 2, lc4 = lane & 3;

    const float* Ag = (const float*)g_att;

    auto load_stage = [&](int s, int k0) {
        float* As = smf + s * STG_W;
        float* Bs = As + STG_A;
#pragma unroll
        for (int it = 0; it < 4; it++) {
            int idx = tid + it * 256;
            int m = idx >> 3, q = idx & 7;
            cp16(s2u(&As[m * A_ST + q * 4]),
                 &Ag[(size_t)(m0 + m) * kD + k0 + q * 4]);
        }
#pragma unroll
        for (int it = 0; it < 4; it++) {
            int idx = tid + it * 256;
            int kk = idx >> 5, nq = idx & 31;
            cp16(s2u(&Bs[kk * B_ST + nq * 4]),
                 &Wo[(size_t)(k0 + kk) * kD + n0 + nq * 4]);
        }
    };

    float acc[4][4][4] = {};

#pragma unroll
    for (int s = 0; s < NSTG; s++) { load_stage(s, s * 32); cp_commit(); }

    const int KT = kD / 32;
    for (int ki = 0; ki < KT; ki++) {
        cp_wait<NSTG - 1>();
        __syncthreads();
        const float* As = smf + (ki % NSTG) * STG_W;
        const float* Bs = As + STG_A;
#pragma unroll
        for (int k8 = 0; k8 < 32; k8 += 8) {
            uint32_t a[4][4];
#pragma unroll
            for (int mf = 0; mf < 4; mf++) {
                int base = (wm + mf * 16 + ln4) * A_ST + k8 + lc4;
                a[mf][0] = f2tf(As[base]);
                a[mf][1] = f2tf(As[base + 8 * A_ST]);
                a[mf][2] = f2tf(As[base + 4]);
                a[mf][3] = f2tf(As[base + 8 * A_ST + 4]);
            }
            uint32_t bb[4][2];
#pragma unroll
            for (int nf = 0; nf < 4; nf++) {
                int base = (k8 + lc4) * B_ST + wn + nf * 8 + ln4;
                bb[nf][0] = f2tf(Bs[base]);
                bb[nf][1] = f2tf(Bs[base + 4 * B_ST]);
            }
#pragma unroll
            for (int mf = 0; mf < 4; mf++)
#pragma unroll
                for (int nf = 0; nf < 4; nf++)
                    mma_tf32(acc[mf][nf], a[mf], bb[nf]);
        }
        __syncthreads();
        int kn = ki + NSTG;
        if (kn < KT) load_stage(ki % NSTG, kn * 32);
        cp_commit();
    }

#pragma unroll
    for (int mf = 0; mf < 4; mf++) {
#pragma unroll
        for (int rp = 0; rp < 2; rp++) {
            const int m = m0 + wm + mf * 16 + ln4 + rp * 8;
#pragma unroll
            for (int nf = 0; nf < 4; nf++) {
                const int n = n0 + wn + nf * 8 + lc4 * 2;
                float v0 = acc[mf][nf][rp * 2 + 0] + bo[n];
                float v1 = acc[mf][nf][rp * 2 + 1] + bo[n + 1];
                *(float2*)&out[(size_t)m * kD + n] = make_float2(v0, v1);
            }
        }
    }
}

// ---------------------------------------------------------------------------
// Launch
// ---------------------------------------------------------------------------
extern "C" void kernel_launch(void* const* d_in, const int* in_sizes, int n_in,
                              void* d_out, int out_size) {
    const float* x  = (const float*)d_in[0];
    const float* rf = (const float*)d_in[2];
    const float* pk = (const float*)d_in[3];
    const float* pv = (const float*)d_in[4];
    const float* Wq = (const float*)d_in[5];
    const float* bq = (const float*)d_in[6];
    const float* Wk = (const float*)d_in[7];
    const float* bk = (const float*)d_in[8];
    const float* Wv = (const float*)d_in[9];
    const float* bv = (const float*)d_in[10];
    const float* Wo = (const float*)d_in[11];
    const float* bo = (const float*)d_in[12];
    float* out = (float*)d_out;

    cudaFuncSetAttribute(qkv_kernel,  cudaFuncAttributeMaxDynamicSharedMemorySize, GEMM_SMEM);
    cudaFuncSetAttribute(out_kernel,  cudaFuncAttributeMaxDynamicSharedMemorySize, GEMM_SMEM);
    cudaFuncSetAttribute(attn_kernel, cudaFuncAttributeMaxDynamicSharedMemorySize, ATTN_SMEM_BYTES);

    copy_past_kernel<<<2048, 256>>>((const float4*)pk, (const float4*)pv);
    qkv_kernel<<<dim3(kNTOT / 128, kM / 128), 256, GEMM_SMEM>>>(x, rf, Wq, bq, Wk, bk, Wv, bv);
    attn_kernel<<<dim3(kLQ / 128, kH, kB), 256, ATTN_SMEM_BYTES>>>();
    out_kernel<<<dim3(kD / 128, kM / 128), 256, GEMM_SMEM>>>(Wo, bo, out);
}

// round 6
// speedup vs baseline: 5.0133x; 1.1167x over previous
#include <cuda_runtime.h>
#include <math.h>
#include <stdint.h>

// Problem constants
namespace {
constexpr int kB    = 4;
constexpr int kLQ   = 1024;
constexpr int kD    = 2048;
constexpr int kH    = 16;
constexpr int kG    = 4;
constexpr int kHD   = 128;
constexpr int kPAST = 1024;
constexpr int kLK   = 2048;
constexpr int kM    = kB * kLQ;          // 4096
constexpr int kNQ   = kD;                // 2048
constexpr int kNKV  = kG * kHD;          // 512
constexpr int kNTOT = kNQ + 2 * kNKV;    // 3072
constexpr float kScale = 0.08838834764831845f; // 1/sqrt(128)
}

// Scratch (tf32 bit patterns)
__device__ uint32_t g_q  [kB * kH * kLQ * kHD];   // pre-scaled by kScale
__device__ uint32_t g_kc [kB * kG * kLK * kHD];
__device__ uint32_t g_vc [kB * kG * kLK * kHD];
__device__ uint32_t g_att[kB * kLQ * kD];
__device__ uint32_t g_x  [kM * kD];               // x in tf32
__device__ uint32_t g_wq [kD * kNQ];
__device__ uint32_t g_wk [kD * kNKV];
__device__ uint32_t g_wv [kD * kNKV];
__device__ uint32_t g_wo [kD * kD];

// ---------------------------------------------------------------------------
// helpers
// ---------------------------------------------------------------------------
__device__ __forceinline__ uint32_t f2tf(float f) {
    uint32_t r;
    asm("cvt.rna.tf32.f32 %0, %1;" : "=r"(r) : "f"(f));
    return r;
}
__device__ __forceinline__ void mma_tf32(float* c, const uint32_t* a, const uint32_t* b) {
    asm volatile(
        "mma.sync.aligned.m16n8k8.row.col.f32.tf32.tf32.f32 "
        "{%0,%1,%2,%3}, {%4,%5,%6,%7}, {%8,%9}, {%0,%1,%2,%3};"
        : "+f"(c[0]), "+f"(c[1]), "+f"(c[2]), "+f"(c[3])
        : "r"(a[0]), "r"(a[1]), "r"(a[2]), "r"(a[3]), "r"(b[0]), "r"(b[1]));
}
__device__ __forceinline__ uint4 cvt4(float4 v) {
    return make_uint4(f2tf(v.x), f2tf(v.y), f2tf(v.z), f2tf(v.w));
}
__device__ __forceinline__ uint32_t s2u(const void* p) {
    return (uint32_t)__cvta_generic_to_shared(p);
}
__device__ __forceinline__ void cp16(uint32_t saddr, const void* gptr) {
    asm volatile("cp.async.cg.shared.global [%0], [%1], 16;"
                 :: "r"(saddr), "l"(gptr));
}
__device__ __forceinline__ void cp_commit() {
    asm volatile("cp.async.commit_group;" ::: "memory");
}
template <int N>
__device__ __forceinline__ void cp_wait() {
    asm volatile("cp.async.wait_group %0;" :: "n"(N) : "memory");
}

// ---------------------------------------------------------------------------
// Kernel 0: convert x + weights to tf32 scratch (one pass, float4 granules)
// ---------------------------------------------------------------------------
namespace {
constexpr int X4  = kM * kD / 4;        // 2,097,152
constexpr int WQ4 = kD * kNQ / 4;       // 1,048,576
constexpr int WK4 = kD * kNKV / 4;      //   262,144
constexpr int WV4 = WK4;
constexpr int WO4 = kD * kD / 4;        // 1,048,576
constexpr int CVT_TOTAL = X4 + WQ4 + WK4 + WV4 + WO4;   // 4,718,592
}

__global__ void cvt_inputs_kernel(const float4* __restrict__ x,
                                  const float4* __restrict__ wq,
                                  const float4* __restrict__ wk,
                                  const float4* __restrict__ wv,
                                  const float4* __restrict__ wo) {
    int i = blockIdx.x * blockDim.x + threadIdx.x;
    if (i >= CVT_TOTAL) return;
    if (i < X4)                        { ((uint4*)g_x )[i]                       = cvt4(x [i]); return; }
    i -= X4;
    if (i < WQ4)                       { ((uint4*)g_wq)[i]                       = cvt4(wq[i]); return; }
    i -= WQ4;
    if (i < WK4)                       { ((uint4*)g_wk)[i]                       = cvt4(wk[i]); return; }
    i -= WK4;
    if (i < WV4)                       { ((uint4*)g_wv)[i]                       = cvt4(wv[i]); return; }
    i -= WV4;
    ((uint4*)g_wo)[i] = cvt4(wo[i]);
}

// ---------------------------------------------------------------------------
// Kernel 1: copy past_k/past_v into caches (convert to tf32)
// ---------------------------------------------------------------------------
__global__ void copy_past_kernel(const float4* __restrict__ pk,
                                 const float4* __restrict__ pv) {
    constexpr int chunk4 = kPAST * kHD / 4;
    constexpr int dst4   = kLK * kHD / 4;
    constexpr int total4 = kB * kG * chunk4;
    int i = blockIdx.x * blockDim.x + threadIdx.x;
    if (i < total4) {
        int cg  = i / chunk4;
        int rem = i - cg * chunk4;
        ((uint4*)g_kc)[cg * dst4 + rem] = cvt4(pk[i]);
        ((uint4*)g_vc)[cg * dst4 + rem] = cvt4(pv[i]);
    }
}

// ---------------------------------------------------------------------------
// GEMM pipeline constants: 128x128x32, 3-stage cp.async, 2 CTAs/SM
// ---------------------------------------------------------------------------
constexpr int A_ST  = 36;    // As[m][k] stride (%32==4 -> a-frag CF)
constexpr int B_ST  = 136;   // Bs[k][n] stride (%32==8 -> b-frag CF)
constexpr int STG_A = 128 * A_ST;
constexpr int STG_B = 32 * B_ST;
constexpr int STG_W = STG_A + STG_B;
constexpr int NSTG  = 3;
constexpr int GEMM_SMEM = NSTG * STG_W * 4;   // 107,520 B (x2 CTAs = 215 KB)

// ---------------------------------------------------------------------------
// Kernel 2: QKV projection GEMM + bias + RoPE + tf32 scatter
// ---------------------------------------------------------------------------
__global__ __launch_bounds__(256, 2) void qkv_kernel(
    const float* __restrict__ rf,
    const float* __restrict__ bq, const float* __restrict__ bk,
    const float* __restrict__ bv) {

    extern __shared__ uint32_t smw[];

    const int n0  = blockIdx.x * 128;
    const int m0  = blockIdx.y * 128;
    const int tid = threadIdx.x;
    const int wid = tid >> 5, lane = tid & 31;
    const int wm = (wid >> 2) * 64;
    const int wn = (wid & 3) * 32;
    const int ln4 = lane >> 2, lc4 = lane & 3;

    const uint32_t* W; const float* bias; int nloc; int Nw; int seg;
    if (n0 < kNQ)              { W = g_wq; bias = bq; nloc = n0;              Nw = kNQ;  seg = 0; }
    else if (n0 < kNQ + kNKV)  { W = g_wk; bias = bk; nloc = n0 - kNQ;        Nw = kNKV; seg = 1; }
    else                       { W = g_wv; bias = bv; nloc = n0 - kNQ - kNKV; Nw = kNKV; seg = 2; }

    auto load_stage = [&](int s, int k0) {
        uint32_t* As = smw + s * STG_W;
        uint32_t* Bs = As + STG_A;
#pragma unroll
        for (int it = 0; it < 4; it++) {
            int idx = tid + it * 256;
            int m = idx >> 3, q = idx & 7;
            cp16(s2u(&As[m * A_ST + q * 4]),
                 &g_x[(size_t)(m0 + m) * kD + k0 + q * 4]);
        }
#pragma unroll
        for (int it = 0; it < 4; it++) {
            int idx = tid + it * 256;
            int kk = idx >> 5, nq = idx & 31;
            cp16(s2u(&Bs[kk * B_ST + nq * 4]),
                 &W[(size_t)(k0 + kk) * Nw + nloc + nq * 4]);
        }
    };

    float acc[4][4][4] = {};

#pragma unroll
    for (int s = 0; s < NSTG; s++) { load_stage(s, s * 32); cp_commit(); }

    const int KT = kD / 32;
    for (int ki = 0; ki < KT; ki++) {
        cp_wait<NSTG - 1>();
        __syncthreads();
        const uint32_t* As = smw + (ki % NSTG) * STG_W;
        const uint32_t* Bs = As + STG_A;
#pragma unroll
        for (int k8 = 0; k8 < 32; k8 += 8) {
            uint32_t a[4][4];
#pragma unroll
            for (int mf = 0; mf < 4; mf++) {
                int base = (wm + mf * 16 + ln4) * A_ST + k8 + lc4;
                a[mf][0] = As[base];
                a[mf][1] = As[base + 8 * A_ST];
                a[mf][2] = As[base + 4];
                a[mf][3] = As[base + 8 * A_ST + 4];
            }
            uint32_t bb[4][2];
#pragma unroll
            for (int nf = 0; nf < 4; nf++) {
                int base = (k8 + lc4) * B_ST + wn + nf * 8 + ln4;
                bb[nf][0] = Bs[base];
                bb[nf][1] = Bs[base + 4 * B_ST];
            }
#pragma unroll
            for (int mf = 0; mf < 4; mf++)
#pragma unroll
                for (int nf = 0; nf < 4; nf++)
                    mma_tf32(acc[mf][nf], a[mf], bb[nf]);
        }
        __syncthreads();
        int kn = ki + NSTG;
        if (kn < KT) load_stage(ki % NSTG, kn * 32);
        cp_commit();
    }

    // Epilogue: bias + RoPE + tf32 scatter
#pragma unroll
    for (int mf = 0; mf < 4; mf++) {
#pragma unroll
        for (int rp = 0; rp < 2; rp++) {
            const int m = m0 + wm + mf * 16 + ln4 + rp * 8;
            const int b = m >> 10;
            const int t = m & (kLQ - 1);
#pragma unroll
            for (int nf = 0; nf < 4; nf++) {
                const int n = nloc + wn + nf * 8 + lc4 * 2;
                float v0 = acc[mf][nf][rp * 2 + 0] + bias[n];
                float v1 = acc[mf][nf][rp * 2 + 1] + bias[n + 1];
                const int d = n & 127;
                if (seg == 0) {
                    const int h = n >> 7;
                    float sn, cs; sincosf(rf[t * (kHD / 2) + (d >> 1)], &sn, &cs);
                    float r0 = v0 * cs - v1 * sn;
                    float r1 = v0 * sn + v1 * cs;
                    uint32_t* dst = &g_q[((size_t)((b * kH + h) * kLQ + t) * kHD) + d];
                    *(uint2*)dst = make_uint2(f2tf(r0 * kScale), f2tf(r1 * kScale));
                } else if (seg == 1) {
                    const int g = n >> 7;
                    float sn, cs; sincosf(rf[t * (kHD / 2) + (d >> 1)], &sn, &cs);
                    float r0 = v0 * cs - v1 * sn;
                    float r1 = v0 * sn + v1 * cs;
                    uint32_t* dst = &g_kc[((size_t)((b * kG + g) * kLK + kPAST + t) * kHD) + d];
                    *(uint2*)dst = make_uint2(f2tf(r0), f2tf(r1));
                } else {
                    const int g = n >> 7;
                    uint32_t* dst = &g_vc[((size_t)((b * kG + g) * kLK + kPAST + t) * kHD) + d];
                    *(uint2*)dst = make_uint2(f2tf(v0), f2tf(v1));
                }
            }
        }
    }
}

// ---------------------------------------------------------------------------
// Kernel 3: flash attention, tf32 HMMA, ping-pong K/V cp.async.
// BQ=128, BK=64, 8 warps x 16 q-rows.
// ---------------------------------------------------------------------------
constexpr int QS_ST = 132;
constexpr int KK_ST = 132;
constexpr int VV_ST = 136;
constexpr int PS_ST = 68;
constexpr int ATTN_WORDS = 128 * QS_ST + 64 * KK_ST + 64 * VV_ST + 128 * PS_ST;
constexpr int ATTN_SMEM_BYTES = ATTN_WORDS * 4;   // 171,008 B

__global__ __launch_bounds__(256, 1) void attn_kernel() {
    extern __shared__ uint32_t smw[];
    uint32_t* Qs = smw;
    uint32_t* Kb = Qs + 128 * QS_ST;
    uint32_t* Vb = Kb + 64 * KK_ST;
    uint32_t* Ps = Vb + 64 * VV_ST;

    const int qb = blockIdx.x;
    const int h  = blockIdx.y;
    const int b  = blockIdx.z;
    const int g  = h >> 2;
    const int t0 = qb * 128;
    const int tid = threadIdx.x;
    const int wid = tid >> 5, lane = tid & 31;
    const int rq = wid * 16;
    const int ln4 = lane >> 2, lc4 = lane & 3;

    const uint32_t* qbase = g_q  + ((size_t)(b * kH + h) * kLQ + t0) * kHD;
    const uint32_t* kbase = g_kc + (size_t)(b * kG + g) * kLK * kHD;
    const uint32_t* vbase = g_vc + (size_t)(b * kG + g) * kLK * kHD;

    // Prologue: Q tile + K(0)
#pragma unroll
    for (int it = 0; it < 16; it++) {
        int idx = tid + it * 256;
        int t = idx >> 5, q = idx & 31;
        cp16(s2u(&Qs[t * QS_ST + q * 4]), &qbase[(size_t)t * kHD + q * 4]);
    }
#pragma unroll
    for (int it = 0; it < 8; it++) {
        int idx = tid + it * 256;
        int key = idx >> 5, q = idx & 31;
        cp16(s2u(&Kb[key * KK_ST + q * 4]), &kbase[(size_t)key * kHD + q * 4]);
    }
    cp_commit();

    float oacc[16][4] = {};
    float mA = -1e30f, lA = 0.f, mB = -1e30f, lB = 0.f;
    const int ntiles = (kPAST + t0) / 64 + 2;

    for (int kt = 0; kt < ntiles; kt++) {
        const int k0 = kt * 64;
        cp_wait<0>();
        __syncthreads();

        // stream V(kt) during S-phase
#pragma unroll
        for (int it = 0; it < 8; it++) {
            int idx = tid + it * 256;
            int key = idx >> 5, q = idx & 31;
            cp16(s2u(&Vb[key * VV_ST + q * 4]),
                 &vbase[(size_t)(k0 + key) * kHD + q * 4]);
        }
        cp_commit();

        // S = Q.K^T
        float sacc[8][4] = {};
#pragma unroll
        for (int k8 = 0; k8 < 16; k8++) {
            const int d0 = k8 * 8;
            uint32_t a[4];
            int qb_ = (rq + ln4) * QS_ST + d0 + lc4;
            a[0] = Qs[qb_];
            a[1] = Qs[qb_ + 8 * QS_ST];
            a[2] = Qs[qb_ + 4];
            a[3] = Qs[qb_ + 8 * QS_ST + 4];
#pragma unroll
            for (int nf = 0; nf < 8; nf++) {
                uint32_t bfr[2];
                int kb_ = (nf * 8 + ln4) * KK_ST + d0 + lc4;
                bfr[0] = Kb[kb_];
                bfr[1] = Kb[kb_ + 4];
                mma_tf32(sacc[nf], a, bfr);
            }
        }

        // causal mask near diagonal
        const int qposA = kPAST + t0 + rq + ln4;
        if (k0 + 63 > kPAST + t0) {
#pragma unroll
            for (int nf = 0; nf < 8; nf++) {
#pragma unroll
                for (int j = 0; j < 2; j++) {
                    int kpos = k0 + nf * 8 + lc4 * 2 + j;
                    if (kpos > qposA)     sacc[nf][j]     = -1e30f;
                    if (kpos > qposA + 8) sacc[nf][2 + j] = -1e30f;
                }
            }
        }

        // online softmax
        float mxA = -1e30f, mxB = -1e30f;
#pragma unroll
        for (int nf = 0; nf < 8; nf++) {
            mxA = fmaxf(mxA, fmaxf(sacc[nf][0], sacc[nf][1]));
            mxB = fmaxf(mxB, fmaxf(sacc[nf][2], sacc[nf][3]));
        }
#pragma unroll
        for (int off = 1; off < 4; off <<= 1) {
            mxA = fmaxf(mxA, __shfl_xor_sync(0xffffffffu, mxA, off));
            mxB = fmaxf(mxB, __shfl_xor_sync(0xffffffffu, mxB, off));
        }
        float mnA = fmaxf(mA, mxA), mnB = fmaxf(mB, mxB);
        float alA = __expf(mA - mnA), alB = __expf(mB - mnB);
        float sumA = 0.f, sumB = 0.f;
#pragma unroll
        for (int nf = 0; nf < 8; nf++) {
            float p0 = __expf(sacc[nf][0] - mnA);
            float p1 = __expf(sacc[nf][1] - mnA);
            float p2 = __expf(sacc[nf][2] - mnB);
            float p3 = __expf(sacc[nf][3] - mnB);
            sumA += p0 + p1; sumB += p2 + p3;
            int pc = nf * 8 + lc4 * 2;
            *(uint2*)&Ps[(rq + ln4) * PS_ST + pc]     = make_uint2(f2tf(p0), f2tf(p1));
            *(uint2*)&Ps[(rq + ln4 + 8) * PS_ST + pc] = make_uint2(f2tf(p2), f2tf(p3));
        }
#pragma unroll
        for (int off = 1; off < 4; off <<= 1) {
            sumA += __shfl_xor_sync(0xffffffffu, sumA, off);
            sumB += __shfl_xor_sync(0xffffffffu, sumB, off);
        }
        lA = lA * alA + sumA;  mA = mnA;
        lB = lB * alB + sumB;  mB = mnB;

#pragma unroll
        for (int nf = 0; nf < 16; nf++) {
            oacc[nf][0] *= alA; oacc[nf][1] *= alA;
            oacc[nf][2] *= alB; oacc[nf][3] *= alB;
        }
        __syncthreads();

        // stream K(kt+1) during O-phase
        if (kt + 1 < ntiles) {
            int kn0 = k0 + 64;
#pragma unroll
            for (int it = 0; it < 8; it++) {
                int idx = tid + it * 256;
                int key = idx >> 5, q = idx & 31;
                cp16(s2u(&Kb[key * KK_ST + q * 4]),
                     &kbase[(size_t)(kn0 + key) * kHD + q * 4]);
            }
        }
        cp_commit();
        cp_wait<1>();
        __syncthreads();

        // O += P.V
#pragma unroll
        for (int kk8 = 0; kk8 < 8; kk8++) {
            const int kk0 = kk8 * 8;
            uint32_t a[4];
            int pb_ = (rq + ln4) * PS_ST + kk0 + lc4;
            a[0] = Ps[pb_];
            a[1] = Ps[pb_ + 8 * PS_ST];
            a[2] = Ps[pb_ + 4];
            a[3] = Ps[pb_ + 8 * PS_ST + 4];
#pragma unroll
            for (int nf = 0; nf < 16; nf++) {
                uint32_t bfr[2];
                int vb_ = (kk0 + lc4) * VV_ST + nf * 8 + ln4;
                bfr[0] = Vb[vb_];
                bfr[1] = Vb[vb_ + 4 * VV_ST];
                mma_tf32(oacc[nf], a, bfr);
            }
        }
    }

    // normalize + store tf32 to g_att
    const float invA = 1.f / lA, invB = 1.f / lB;
    const int tA = t0 + rq + ln4;
    uint32_t* dA = &g_att[((size_t)(b * kLQ + tA)) * kD + h * kHD];
    uint32_t* dB = &g_att[((size_t)(b * kLQ + tA + 8)) * kD + h * kHD];
#pragma unroll
    for (int nf = 0; nf < 16; nf++) {
        int col = nf * 8 + lc4 * 2;
        *(uint2*)&dA[col] = make_uint2(f2tf(oacc[nf][0] * invA), f2tf(oacc[nf][1] * invA));
        *(uint2*)&dB[col] = make_uint2(f2tf(oacc[nf][2] * invB), f2tf(oacc[nf][3] * invB));
    }
}

// ---------------------------------------------------------------------------
// Kernel 4: output GEMM (A = g_att, B = g_wo, both tf32), 3-stage, 2 CTA/SM
// ---------------------------------------------------------------------------
__global__ __launch_bounds__(256, 2) void out_kernel(
    const float* __restrict__ bo, float* __restrict__ out) {

    extern __shared__ uint32_t smw[];

    const int n0  = blockIdx.x * 128;
    const int m0  = blockIdx.y * 128;
    const int tid = threadIdx.x;
    const int wid = tid >> 5, lane = tid & 31;
    const int wm = (wid >> 2) * 64;
    const int wn = (wid & 3) * 32;
    const int ln4 = lane >> 2, lc4 = lane & 3;

    auto load_stage = [&](int s, int k0) {
        uint32_t* As = smw + s * STG_W;
        uint32_t* Bs = As + STG_A;
#pragma unroll
        for (int it = 0; it < 4; it++) {
            int idx = tid + it * 256;
            int m = idx >> 3, q = idx & 7;
            cp16(s2u(&As[m * A_ST + q * 4]),
                 &g_att[(size_t)(m0 + m) * kD + k0 + q * 4]);
        }
#pragma unroll
        for (int it = 0; it < 4; it++) {
            int idx = tid + it * 256;
            int kk = idx >> 5, nq = idx & 31;
            cp16(s2u(&Bs[kk * B_ST + nq * 4]),
                 &g_wo[(size_t)(k0 + kk) * kD + n0 + nq * 4]);
        }
    };

    float acc[4][4][4] = {};

#pragma unroll
    for (int s = 0; s < NSTG; s++) { load_stage(s, s * 32); cp_commit(); }

    const int KT = kD / 32;
    for (int ki = 0; ki < KT; ki++) {
        cp_wait<NSTG - 1>();
        __syncthreads();
        const uint32_t* As = smw + (ki % NSTG) * STG_W;
        const uint32_t* Bs = As + STG_A;
#pragma unroll
        for (int k8 = 0; k8 < 32; k8 += 8) {
            uint32_t a[4][4];
#pragma unroll
            for (int mf = 0; mf < 4; mf++) {
                int base = (wm + mf * 16 + ln4) * A_ST + k8 + lc4;
                a[mf][0] = As[base];
                a[mf][1] = As[base + 8 * A_ST];
                a[mf][2] = As[base + 4];
                a[mf][3] = As[base + 8 * A_ST + 4];
            }
            uint32_t bb[4][2];
#pragma unroll
            for (int nf = 0; nf < 4; nf++) {
                int base = (k8 + lc4) * B_ST + wn + nf * 8 + ln4;
                bb[nf][0] = Bs[base];
                bb[nf][1] = Bs[base + 4 * B_ST];
            }
#pragma unroll
            for (int mf = 0; mf < 4; mf++)
#pragma unroll
                for (int nf = 0; nf < 4; nf++)
                    mma_tf32(acc[mf][nf], a[mf], bb[nf]);
        }
        __syncthreads();
        int kn = ki + NSTG;
        if (kn < KT) load_stage(ki % NSTG, kn * 32);
        cp_commit();
    }

#pragma unroll
    for (int mf = 0; mf < 4; mf++) {
#pragma unroll
        for (int rp = 0; rp < 2; rp++) {
            const int m = m0 + wm + mf * 16 + ln4 + rp * 8;
#pragma unroll
            for (int nf = 0; nf < 4; nf++) {
                const int n = n0 + wn + nf * 8 + lc4 * 2;
                float v0 = acc[mf][nf][rp * 2 + 0] + bo[n];
                float v1 = acc[mf][nf][rp * 2 + 1] + bo[n + 1];
                *(float2*)&out[(size_t)m * kD + n] = make_float2(v0, v1);
            }
        }
    }
}

// ---------------------------------------------------------------------------
// Launch
// ---------------------------------------------------------------------------
extern "C" void kernel_launch(void* const* d_in, const int* in_sizes, int n_in,
                              void* d_out, int out_size) {
    const float* x  = (const float*)d_in[0];
    const float* rf = (const float*)d_in[2];
    const float* pk = (const float*)d_in[3];
    const float* pv = (const float*)d_in[4];
    const float* Wq = (const float*)d_in[5];
    const float* bq = (const float*)d_in[6];
    const float* Wk = (const float*)d_in[7];
    const float* bk = (const float*)d_in[8];
    const float* Wv = (const float*)d_in[9];
    const float* bv = (const float*)d_in[10];
    const float* Wo = (const float*)d_in[11];
    const float* bo = (const float*)d_in[12];
    float* out = (float*)d_out;

    cudaFuncSetAttribute(qkv_kernel,  cudaFuncAttributeMaxDynamicSharedMemorySize, GEMM_SMEM);
    cudaFuncSetAttribute(out_kernel,  cudaFuncAttributeMaxDynamicSharedMemorySize, GEMM_SMEM);
    cudaFuncSetAttribute(attn_kernel, cudaFuncAttributeMaxDynamicSharedMemorySize, ATTN_SMEM_BYTES);

    cvt_inputs_kernel<<<(CVT_TOTAL + 255) / 256, 256>>>(
        (const float4*)x, (const float4*)Wq, (const float4*)Wk,
        (const float4*)Wv, (const float4*)Wo);
    copy_past_kernel<<<2048, 256>>>((const float4*)pk, (const float4*)pv);
    qkv_kernel<<<dim3(kNTOT / 128, kM / 128), 256, GEMM_SMEM>>>(rf, bq, bk, bv);
    attn_kernel<<<dim3(kLQ / 128, kH, kB), 256, ATTN_SMEM_BYTES>>>();
    out_kernel<<<dim3(kD / 128, kM / 128), 256, GEMM_SMEM>>>(bo, out);
}

// round 7
// speedup vs baseline: 5.1210x; 1.0215x over previous
#include <cuda_runtime.h>
#include <math.h>
#include <stdint.h>

// Problem constants
namespace {
constexpr int kB    = 4;
constexpr int kLQ   = 1024;
constexpr int kD    = 2048;
constexpr int kH    = 16;
constexpr int kG    = 4;
constexpr int kHD   = 128;
constexpr int kPAST = 1024;
constexpr int kLK   = 2048;
constexpr int kM    = kB * kLQ;          // 4096
constexpr int kNQ   = kD;                // 2048
constexpr int kNKV  = kG * kHD;          // 512
constexpr int kNTOT = kNQ + 2 * kNKV;    // 3072
constexpr float kScale = 0.08838834764831845f; // 1/sqrt(128)
}

// Scratch (tf32 bit patterns)
__device__ uint32_t g_q  [kB * kH * kLQ * kHD];   // pre-scaled by kScale
__device__ uint32_t g_kc [kB * kG * kLK * kHD];   // (b,g,p,d)
__device__ uint32_t g_vt [kB * kG * kHD * kLK];   // (b,g,d,p)  TRANSPOSED
__device__ uint32_t g_att[kB * kLQ * kD];
__device__ uint32_t g_x  [kM * kD];
__device__ uint32_t g_wq [kD * kNQ];
__device__ uint32_t g_wk [kD * kNKV];
__device__ uint32_t g_wv [kD * kNKV];
__device__ uint32_t g_wo [kD * kD];

// ---------------------------------------------------------------------------
// helpers
// ---------------------------------------------------------------------------
__device__ __forceinline__ uint32_t f2tf(float f) {
    uint32_t r;
    asm("cvt.rna.tf32.f32 %0, %1;" : "=r"(r) : "f"(f));
    return r;
}
__device__ __forceinline__ void mma_tf32(float* c, const uint32_t* a, const uint32_t* b) {
    asm volatile(
        "mma.sync.aligned.m16n8k8.row.col.f32.tf32.tf32.f32 "
        "{%0,%1,%2,%3}, {%4,%5,%6,%7}, {%8,%9}, {%0,%1,%2,%3};"
        : "+f"(c[0]), "+f"(c[1]), "+f"(c[2]), "+f"(c[3])
        : "r"(a[0]), "r"(a[1]), "r"(a[2]), "r"(a[3]), "r"(b[0]), "r"(b[1]));
}
__device__ __forceinline__ uint4 cvt4(float4 v) {
    return make_uint4(f2tf(v.x), f2tf(v.y), f2tf(v.z), f2tf(v.w));
}
__device__ __forceinline__ uint32_t s2u(const void* p) {
    return (uint32_t)__cvta_generic_to_shared(p);
}
__device__ __forceinline__ void cp16(uint32_t saddr, const void* gptr) {
    asm volatile("cp.async.cg.shared.global [%0], [%1], 16;"
                 :: "r"(saddr), "l"(gptr));
}
__device__ __forceinline__ void cp_commit() {
    asm volatile("cp.async.commit_group;" ::: "memory");
}
template <int N>
__device__ __forceinline__ void cp_wait() {
    asm volatile("cp.async.wait_group %0;" :: "n"(N) : "memory");
}
// tf32 fragments via b16 ldmatrix (each lane reg = one tf32 word)
__device__ __forceinline__ void ldsm_x4(uint32_t* r, uint32_t saddr) {
    asm volatile("ldmatrix.sync.aligned.m8n8.x4.shared.b16 {%0,%1,%2,%3}, [%4];"
        : "=r"(r[0]), "=r"(r[1]), "=r"(r[2]), "=r"(r[3]) : "r"(saddr));
}
__device__ __forceinline__ void ldsm_x2(uint32_t* r, uint32_t saddr) {
    asm volatile("ldmatrix.sync.aligned.m8n8.x2.shared.b16 {%0,%1}, [%2];"
        : "=r"(r[0]), "=r"(r[1]) : "r"(saddr));
}

// ---------------------------------------------------------------------------
// Kernel 0: convert x + weights to tf32 scratch
// ---------------------------------------------------------------------------
namespace {
constexpr int X4  = kM * kD / 4;
constexpr int WQ4 = kD * kNQ / 4;
constexpr int WK4 = kD * kNKV / 4;
constexpr int WV4 = WK4;
constexpr int CVT_TOTAL = X4 + WQ4 + WK4 + WV4 + kD * kD / 4;
}

__global__ void cvt_inputs_kernel(const float4* __restrict__ x,
                                  const float4* __restrict__ wq,
                                  const float4* __restrict__ wk,
                                  const float4* __restrict__ wv,
                                  const float4* __restrict__ wo) {
    int i = blockIdx.x * blockDim.x + threadIdx.x;
    if (i >= CVT_TOTAL) return;
    if (i < X4)  { ((uint4*)g_x )[i] = cvt4(x [i]); return; }
    i -= X4;
    if (i < WQ4) { ((uint4*)g_wq)[i] = cvt4(wq[i]); return; }
    i -= WQ4;
    if (i < WK4) { ((uint4*)g_wk)[i] = cvt4(wk[i]); return; }
    i -= WK4;
    if (i < WV4) { ((uint4*)g_wv)[i] = cvt4(wv[i]); return; }
    i -= WV4;
    ((uint4*)g_wo)[i] = cvt4(wo[i]);
}

// ---------------------------------------------------------------------------
// Kernel 1: copy past K (straight) + past V (transposed) into caches
// grid (kHD/32, kPAST/32, kB*kG), block (32, 8)
// ---------------------------------------------------------------------------
__global__ void copy_past_kernel(const float* __restrict__ pk,
                                 const float* __restrict__ pv) {
    __shared__ float t[32][33];
    const int bg = blockIdx.z;
    const int p0 = blockIdx.y * 32;
    const int d0 = blockIdx.x * 32;
    const int tx = threadIdx.x, ty = threadIdx.y;
#pragma unroll
    for (int r = 0; r < 4; r++) {
        int p = p0 + ty + r * 8;
        size_t src = ((size_t)bg * kPAST + p) * kHD + d0 + tx;
        g_kc[((size_t)bg * kLK + p) * kHD + d0 + tx] = f2tf(pk[src]);
        t[ty + r * 8][tx] = pv[src];
    }
    __syncthreads();
#pragma unroll
    for (int r = 0; r < 4; r++) {
        int d = d0 + ty + r * 8;
        g_vt[((size_t)bg * kHD + d) * kLK + p0 + tx] = f2tf(t[tx][ty + r * 8]);
    }
}

// ---------------------------------------------------------------------------
// GEMM pipeline constants: 128x128x32, 3-stage cp.async, 2 CTAs/SM
// ---------------------------------------------------------------------------
constexpr int A_ST  = 36;
constexpr int B_ST  = 136;
constexpr int STG_A = 128 * A_ST;
constexpr int STG_B = 32 * B_ST;
constexpr int STG_W = STG_A + STG_B;
constexpr int NSTG  = 3;
constexpr int GEMM_SMEM = NSTG * STG_W * 4;

// ---------------------------------------------------------------------------
// Kernel 2: QKV projection GEMM + bias + RoPE + tf32 scatter
// ---------------------------------------------------------------------------
__global__ __launch_bounds__(256, 2) void qkv_kernel(
    const float* __restrict__ rf,
    const float* __restrict__ bq, const float* __restrict__ bk,
    const float* __restrict__ bv) {

    extern __shared__ uint32_t smw[];

    const int n0  = blockIdx.x * 128;
    const int m0  = blockIdx.y * 128;
    const int tid = threadIdx.x;
    const int wid = tid >> 5, lane = tid & 31;
    const int wm = (wid >> 2) * 64;
    const int wn = (wid & 3) * 32;
    const int ln4 = lane >> 2, lc4 = lane & 3;

    const uint32_t* W; const float* bias; int nloc; int Nw; int seg;
    if (n0 < kNQ)              { W = g_wq; bias = bq; nloc = n0;              Nw = kNQ;  seg = 0; }
    else if (n0 < kNQ + kNKV)  { W = g_wk; bias = bk; nloc = n0 - kNQ;        Nw = kNKV; seg = 1; }
    else                       { W = g_wv; bias = bv; nloc = n0 - kNQ - kNKV; Nw = kNKV; seg = 2; }

    auto load_stage = [&](int s, int k0) {
        uint32_t* As = smw + s * STG_W;
        uint32_t* Bs = As + STG_A;
#pragma unroll
        for (int it = 0; it < 4; it++) {
            int idx = tid + it * 256;
            int m = idx >> 3, q = idx & 7;
            cp16(s2u(&As[m * A_ST + q * 4]),
                 &g_x[(size_t)(m0 + m) * kD + k0 + q * 4]);
        }
#pragma unroll
        for (int it = 0; it < 4; it++) {
            int idx = tid + it * 256;
            int kk = idx >> 5, nq = idx & 31;
            cp16(s2u(&Bs[kk * B_ST + nq * 4]),
                 &W[(size_t)(k0 + kk) * Nw + nloc + nq * 4]);
        }
    };

    float acc[4][4][4] = {};

#pragma unroll
    for (int s = 0; s < NSTG; s++) { load_stage(s, s * 32); cp_commit(); }

    const int KT = kD / 32;
    for (int ki = 0; ki < KT; ki++) {
        cp_wait<NSTG - 1>();
        __syncthreads();
        const uint32_t* As = smw + (ki % NSTG) * STG_W;
        const uint32_t* Bs = As + STG_A;
#pragma unroll
        for (int k8 = 0; k8 < 32; k8 += 8) {
            uint32_t a[4][4];
#pragma unroll
            for (int mf = 0; mf < 4; mf++) {
                int base = (wm + mf * 16 + ln4) * A_ST + k8 + lc4;
                a[mf][0] = As[base];
                a[mf][1] = As[base + 8 * A_ST];
                a[mf][2] = As[base + 4];
                a[mf][3] = As[base + 8 * A_ST + 4];
            }
            uint32_t bb[4][2];
#pragma unroll
            for (int nf = 0; nf < 4; nf++) {
                int base = (k8 + lc4) * B_ST + wn + nf * 8 + ln4;
                bb[nf][0] = Bs[base];
                bb[nf][1] = Bs[base + 4 * B_ST];
            }
#pragma unroll
            for (int mf = 0; mf < 4; mf++)
#pragma unroll
                for (int nf = 0; nf < 4; nf++)
                    mma_tf32(acc[mf][nf], a[mf], bb[nf]);
        }
        __syncthreads();
        int kn = ki + NSTG;
        if (kn < KT) load_stage(ki % NSTG, kn * 32);
        cp_commit();
    }

    // Epilogue: bias + RoPE + tf32 scatter
#pragma unroll
    for (int mf = 0; mf < 4; mf++) {
#pragma unroll
        for (int rp = 0; rp < 2; rp++) {
            const int m = m0 + wm + mf * 16 + ln4 + rp * 8;
            const int b = m >> 10;
            const int t = m & (kLQ - 1);
#pragma unroll
            for (int nf = 0; nf < 4; nf++) {
                const int n = nloc + wn + nf * 8 + lc4 * 2;
                float v0 = acc[mf][nf][rp * 2 + 0] + bias[n];
                float v1 = acc[mf][nf][rp * 2 + 1] + bias[n + 1];
                const int d = n & 127;
                if (seg == 0) {
                    const int h = n >> 7;
                    float sn, cs; sincosf(rf[t * (kHD / 2) + (d >> 1)], &sn, &cs);
                    float r0 = v0 * cs - v1 * sn;
                    float r1 = v0 * sn + v1 * cs;
                    uint32_t* dst = &g_q[((size_t)((b * kH + h) * kLQ + t) * kHD) + d];
                    *(uint2*)dst = make_uint2(f2tf(r0 * kScale), f2tf(r1 * kScale));
                } else if (seg == 1) {
                    const int g = n >> 7;
                    float sn, cs; sincosf(rf[t * (kHD / 2) + (d >> 1)], &sn, &cs);
                    float r0 = v0 * cs - v1 * sn;
                    float r1 = v0 * sn + v1 * cs;
                    uint32_t* dst = &g_kc[((size_t)((b * kG + g) * kLK + kPAST + t) * kHD) + d];
                    *(uint2*)dst = make_uint2(f2tf(r0), f2tf(r1));
                } else {
                    const int g = n >> 7;
                    // transposed V: (b,g,d,p)
                    size_t base = ((size_t)(b * kG + g) * kHD + d) * kLK + kPAST + t;
                    g_vt[base]       = f2tf(v0);
                    g_vt[base + kLK] = f2tf(v1);
                }
            }
        }
    }
}

// ---------------------------------------------------------------------------
// Kernel 3: flash attention, tf32 HMMA, m32 warp tiles + ldmatrix.
// BQ=128, BK=64; warp grid 4m x 2n; cross-warp softmax via smem partials.
// ---------------------------------------------------------------------------
constexpr int QS_ST = 132;   // [t][d]   (r*132)%32 == 4r -> LDSM CF
constexpr int KK_ST = 132;   // [key][d]
constexpr int VT_ST = 68;    // [d][key]
constexpr int PS_ST = 68;    // [row][key]
constexpr int ATTN_WORDS = 128 * QS_ST + 64 * KK_ST + 128 * VT_ST + 128 * PS_ST + 4 * 128;
constexpr int ATTN_SMEM_BYTES = ATTN_WORDS * 4;   // 173,056 B

__global__ __launch_bounds__(256, 1) void attn_kernel() {
    extern __shared__ uint32_t smw[];
    uint32_t* Qs = smw;
    uint32_t* Kb = Qs + 128 * QS_ST;
    uint32_t* Vt = Kb + 64 * KK_ST;
    uint32_t* Ps = Vt + 128 * VT_ST;
    float*   red = (float*)(Ps + 128 * PS_ST);   // [2 sel][2 wn2][128 rows]

    const int qb = blockIdx.x;
    const int h  = blockIdx.y;
    const int b  = blockIdx.z;
    const int g  = h >> 2;
    const int t0 = qb * 128;
    const int tid = threadIdx.x;
    const int wid = tid >> 5, lane = tid & 31;
    const int wm2 = wid >> 1;         // 0..3 (m warp)
    const int wn2 = wid & 1;          // 0..1 (n warp)
    const int arow = wm2 * 32;
    const int ln4 = lane >> 2, lc4 = lane & 3;
    const int lx  = lane & 15, lxt = (lane >> 4) << 2;          // x4 addr parts
    const int ly  = lane & 7,  lyt = ((lane >> 3) & 1) << 2;    // x2 addr parts

    const uint32_t qs_b = s2u(Qs), kb_b = s2u(Kb), vt_b = s2u(Vt), ps_b = s2u(Ps);

    const uint32_t* qbase  = g_q  + ((size_t)(b * kH + h) * kLQ + t0) * kHD;
    const uint32_t* kbase  = g_kc + (size_t)(b * kG + g) * kLK * kHD;
    const uint32_t* vtbase = g_vt + (size_t)(b * kG + g) * kHD * kLK;

    // Prologue: Q tile + K(0)
#pragma unroll
    for (int it = 0; it < 16; it++) {
        int idx = tid + it * 256;
        int t = idx >> 5, q = idx & 31;
        cp16(qs_b + (t * QS_ST + q * 4) * 4, &qbase[(size_t)t * kHD + q * 4]);
    }
#pragma unroll
    for (int it = 0; it < 8; it++) {
        int idx = tid + it * 256;
        int key = idx >> 5, q = idx & 31;
        cp16(kb_b + (key * KK_ST + q * 4) * 4, &kbase[(size_t)key * kHD + q * 4]);
    }
    cp_commit();

    float oacc[2][8][4] = {};
    float m_i[4], l_i[4];
#pragma unroll
    for (int i = 0; i < 4; i++) { m_i[i] = -1e30f; l_i[i] = 0.f; }

    const int ntiles = (kPAST + t0) / 64 + 2;

    for (int kt = 0; kt < ntiles; kt++) {
        const int k0 = kt * 64;
        cp_wait<0>();
        __syncthreads();

        // stream V(kt): 128 d-rows x 64 keys (transposed layout)
#pragma unroll
        for (int it = 0; it < 8; it++) {
            int idx = tid + it * 256;
            int row = idx >> 4, c = (idx & 15) << 2;
            cp16(vt_b + (row * VT_ST + c) * 4,
                 &vtbase[(size_t)row * kLK + k0 + c]);
        }
        cp_commit();

        // S = Q.K^T  — warp tile m32 x n32, k=128
        float sacc[2][4][4] = {};
#pragma unroll
        for (int k8 = 0; k8 < 16; k8++) {
            const int d0 = k8 * 8;
            uint32_t a[2][4], bb[4][2];
#pragma unroll
            for (int mf2 = 0; mf2 < 2; mf2++)
                ldsm_x4(a[mf2], qs_b + ((arow + mf2 * 16 + lx) * QS_ST + d0 + lxt) * 4);
#pragma unroll
            for (int nf = 0; nf < 4; nf++)
                ldsm_x2(bb[nf], kb_b + ((wn2 * 32 + nf * 8 + ly) * KK_ST + d0 + lyt) * 4);
#pragma unroll
            for (int mf2 = 0; mf2 < 2; mf2++)
#pragma unroll
                for (int nf = 0; nf < 4; nf++)
                    mma_tf32(sacc[mf2][nf], a[mf2], bb[nf]);
        }

        // causal mask near diagonal
        if (k0 + 63 > kPAST + t0) {
#pragma unroll
            for (int mf2 = 0; mf2 < 2; mf2++) {
                const int qpos0 = kPAST + t0 + arow + mf2 * 16 + ln4;
#pragma unroll
                for (int nf = 0; nf < 4; nf++)
#pragma unroll
                    for (int j = 0; j < 2; j++) {
                        int kpos = k0 + wn2 * 32 + nf * 8 + lc4 * 2 + j;
                        if (kpos > qpos0)     sacc[mf2][nf][j]     = -1e30f;
                        if (kpos > qpos0 + 8) sacc[mf2][nf][2 + j] = -1e30f;
                    }
            }
        }

        // ---- softmax: per-warp partial (32 keys) + cross-warp exchange ----
        float pmax[4];
#pragma unroll
        for (int mf2 = 0; mf2 < 2; mf2++)
#pragma unroll
            for (int rh = 0; rh < 2; rh++) {
                float v = -1e30f;
#pragma unroll
                for (int nf = 0; nf < 4; nf++)
                    v = fmaxf(v, fmaxf(sacc[mf2][nf][rh * 2], sacc[mf2][nf][rh * 2 + 1]));
                pmax[mf2 * 2 + rh] = v;
            }
#pragma unroll
        for (int i = 0; i < 4; i++) {
            pmax[i] = fmaxf(pmax[i], __shfl_xor_sync(0xffffffffu, pmax[i], 1));
            pmax[i] = fmaxf(pmax[i], __shfl_xor_sync(0xffffffffu, pmax[i], 2));
        }
        if (lc4 == 0) {
#pragma unroll
            for (int i = 0; i < 4; i++)
                red[(0 * 2 + wn2) * 128 + arow + (i >> 1) * 16 + (i & 1) * 8 + ln4] = pmax[i];
        }
        __syncthreads();

        float mn[4], alpha[4];
#pragma unroll
        for (int i = 0; i < 4; i++) {
            int row = arow + (i >> 1) * 16 + (i & 1) * 8 + ln4;
            float omax = red[(0 * 2 + (wn2 ^ 1)) * 128 + row];
            mn[i] = fmaxf(m_i[i], fmaxf(pmax[i], omax));
            alpha[i] = __expf(m_i[i] - mn[i]);
            m_i[i] = mn[i];
        }

        float psum[4] = {0.f, 0.f, 0.f, 0.f};
#pragma unroll
        for (int mf2 = 0; mf2 < 2; mf2++)
#pragma unroll
            for (int nf = 0; nf < 4; nf++) {
                float p0 = __expf(sacc[mf2][nf][0] - mn[mf2 * 2 + 0]);
                float p1 = __expf(sacc[mf2][nf][1] - mn[mf2 * 2 + 0]);
                float p2 = __expf(sacc[mf2][nf][2] - mn[mf2 * 2 + 1]);
                float p3 = __expf(sacc[mf2][nf][3] - mn[mf2 * 2 + 1]);
                psum[mf2 * 2 + 0] += p0 + p1;
                psum[mf2 * 2 + 1] += p2 + p3;
                int col = wn2 * 32 + nf * 8 + lc4 * 2;
                *(uint2*)&Ps[(arow + mf2 * 16 + ln4) * PS_ST + col] =
                    make_uint2(f2tf(p0), f2tf(p1));
                *(uint2*)&Ps[(arow + mf2 * 16 + ln4 + 8) * PS_ST + col] =
                    make_uint2(f2tf(p2), f2tf(p3));
            }
#pragma unroll
        for (int i = 0; i < 4; i++) {
            psum[i] += __shfl_xor_sync(0xffffffffu, psum[i], 1);
            psum[i] += __shfl_xor_sync(0xffffffffu, psum[i], 2);
        }
        if (lc4 == 0) {
#pragma unroll
            for (int i = 0; i < 4; i++)
                red[(1 * 2 + wn2) * 128 + arow + (i >> 1) * 16 + (i & 1) * 8 + ln4] = psum[i];
        }
        __syncthreads();
#pragma unroll
        for (int i = 0; i < 4; i++) {
            int row = arow + (i >> 1) * 16 + (i & 1) * 8 + ln4;
            l_i[i] = l_i[i] * alpha[i] + psum[i] + red[(1 * 2 + (wn2 ^ 1)) * 128 + row];
        }

        // rescale O accumulators
#pragma unroll
        for (int mf2 = 0; mf2 < 2; mf2++)
#pragma unroll
            for (int nf = 0; nf < 8; nf++) {
                oacc[mf2][nf][0] *= alpha[mf2 * 2];
                oacc[mf2][nf][1] *= alpha[mf2 * 2];
                oacc[mf2][nf][2] *= alpha[mf2 * 2 + 1];
                oacc[mf2][nf][3] *= alpha[mf2 * 2 + 1];
            }

        // stream K(kt+1) during O-phase
        if (kt + 1 < ntiles) {
            int kn0 = k0 + 64;
#pragma unroll
            for (int it = 0; it < 8; it++) {
                int idx = tid + it * 256;
                int key = idx >> 5, q = idx & 31;
                cp16(kb_b + (key * KK_ST + q * 4) * 4,
                     &kbase[(size_t)(kn0 + key) * kHD + q * 4]);
            }
        }
        cp_commit();
        cp_wait<1>();       // V(kt) resident
        __syncthreads();

        // O += P.V — warp tile m32 x n64, k=64
#pragma unroll
        for (int kk8 = 0; kk8 < 8; kk8++) {
            const int kk0 = kk8 * 8;
            uint32_t a[2][4], bb[8][2];
#pragma unroll
            for (int mf2 = 0; mf2 < 2; mf2++)
                ldsm_x4(a[mf2], ps_b + ((arow + mf2 * 16 + lx) * PS_ST + kk0 + lxt) * 4);
#pragma unroll
            for (int nf = 0; nf < 8; nf++)
                ldsm_x2(bb[nf], vt_b + ((wn2 * 64 + nf * 8 + ly) * VT_ST + kk0 + lyt) * 4);
#pragma unroll
            for (int mf2 = 0; mf2 < 2; mf2++)
#pragma unroll
                for (int nf = 0; nf < 8; nf++)
                    mma_tf32(oacc[mf2][nf], a[mf2], bb[nf]);
        }
    }

    // normalize + store tf32 to g_att
#pragma unroll
    for (int mf2 = 0; mf2 < 2; mf2++) {
        const float inv0 = 1.f / l_i[mf2 * 2];
        const float inv1 = 1.f / l_i[mf2 * 2 + 1];
        const int rowA = t0 + arow + mf2 * 16 + ln4;
        uint32_t* dA = &g_att[((size_t)(b * kLQ + rowA)) * kD + h * kHD];
        uint32_t* dB = &g_att[((size_t)(b * kLQ + rowA + 8)) * kD + h * kHD];
#pragma unroll
        for (int nf = 0; nf < 8; nf++) {
            int col = wn2 * 64 + nf * 8 + lc4 * 2;
            *(uint2*)&dA[col] = make_uint2(f2tf(oacc[mf2][nf][0] * inv0),
                                           f2tf(oacc[mf2][nf][1] * inv0));
            *(uint2*)&dB[col] = make_uint2(f2tf(oacc[mf2][nf][2] * inv1),
                                           f2tf(oacc[mf2][nf][3] * inv1));
        }
    }
}

// ---------------------------------------------------------------------------
// Kernel 4: output GEMM (A = g_att, B = g_wo, both tf32), 3-stage, 2 CTA/SM
// ---------------------------------------------------------------------------
__global__ __launch_bounds__(256, 2) void out_kernel(
    const float* __restrict__ bo, float* __restrict__ out) {

    extern __shared__ uint32_t smw[];

    const int n0  = blockIdx.x * 128;
    const int m0  = blockIdx.y * 128;
    const int tid = threadIdx.x;
    const int wid = tid >> 5, lane = tid & 31;
    const int wm = (wid >> 2) * 64;
    const int wn = (wid & 3) * 32;
    const int ln4 = lane >> 2, lc4 = lane & 3;

    auto load_stage = [&](int s, int k0) {
        uint32_t* As = smw + s * STG_W;
        uint32_t* Bs = As + STG_A;
#pragma unroll
        for (int it = 0; it < 4; it++) {
            int idx = tid + it * 256;
            int m = idx >> 3, q = idx & 7;
            cp16(s2u(&As[m * A_ST + q * 4]),
                 &g_att[(size_t)(m0 + m) * kD + k0 + q * 4]);
        }
#pragma unroll
        for (int it = 0; it < 4; it++) {
            int idx = tid + it * 256;
            int kk = idx >> 5, nq = idx & 31;
            cp16(s2u(&Bs[kk * B_ST + nq * 4]),
                 &g_wo[(size_t)(k0 + kk) * kD + n0 + nq * 4]);
        }
    };

    float acc[4][4][4] = {};

#pragma unroll
    for (int s = 0; s < NSTG; s++) { load_stage(s, s * 32); cp_commit(); }

    const int KT = kD / 32;
    for (int ki = 0; ki < KT; ki++) {
        cp_wait<NSTG - 1>();
        __syncthreads();
        const uint32_t* As = smw + (ki % NSTG) * STG_W;
        const uint32_t* Bs = As + STG_A;
#pragma unroll
        for (int k8 = 0; k8 < 32; k8 += 8) {
            uint32_t a[4][4];
#pragma unroll
            for (int mf = 0; mf < 4; mf++) {
                int base = (wm + mf * 16 + ln4) * A_ST + k8 + lc4;
                a[mf][0] = As[base];
                a[mf][1] = As[base + 8 * A_ST];
                a[mf][2] = As[base + 4];
                a[mf][3] = As[base + 8 * A_ST + 4];
            }
            uint32_t bb[4][2];
#pragma unroll
            for (int nf = 0; nf < 4; nf++) {
                int base = (k8 + lc4) * B_ST + wn + nf * 8 + ln4;
                bb[nf][0] = Bs[base];
                bb[nf][1] = Bs[base + 4 * B_ST];
            }
#pragma unroll
            for (int mf = 0; mf < 4; mf++)
#pragma unroll
                for (int nf = 0; nf < 4; nf++)
                    mma_tf32(acc[mf][nf], a[mf], bb[nf]);
        }
        __syncthreads();
        int kn = ki + NSTG;
        if (kn < KT) load_stage(ki % NSTG, kn * 32);
        cp_commit();
    }

#pragma unroll
    for (int mf = 0; mf < 4; mf++) {
#pragma unroll
        for (int rp = 0; rp < 2; rp++) {
            const int m = m0 + wm + mf * 16 + ln4 + rp * 8;
#pragma unroll
            for (int nf = 0; nf < 4; nf++) {
                const int n = n0 + wn + nf * 8 + lc4 * 2;
                float v0 = acc[mf][nf][rp * 2 + 0] + bo[n];
                float v1 = acc[mf][nf][rp * 2 + 1] + bo[n + 1];
                *(float2*)&out[(size_t)m * kD + n] = make_float2(v0, v1);
            }
        }
    }
}

// ---------------------------------------------------------------------------
// Launch
// ---------------------------------------------------------------------------
extern "C" void kernel_launch(void* const* d_in, const int* in_sizes, int n_in,
                              void* d_out, int out_size) {
    const float* x  = (const float*)d_in[0];
    const float* rf = (const float*)d_in[2];
    const float* pk = (const float*)d_in[3];
    const float* pv = (const float*)d_in[4];
    const float* Wq = (const float*)d_in[5];
    const float* bq = (const float*)d_in[6];
    const float* Wk = (const float*)d_in[7];
    const float* bk = (const float*)d_in[8];
    const float* Wv = (const float*)d_in[9];
    const float* bv = (const float*)d_in[10];
    const float* Wo = (const float*)d_in[11];
    const float* bo = (const float*)d_in[12];
    float* out = (float*)d_out;

    cudaFuncSetAttribute(qkv_kernel,  cudaFuncAttributeMaxDynamicSharedMemorySize, GEMM_SMEM);
    cudaFuncSetAttribute(out_kernel,  cudaFuncAttributeMaxDynamicSharedMemorySize, GEMM_SMEM);
    cudaFuncSetAttribute(attn_kernel, cudaFuncAttributeMaxDynamicSharedMemorySize, ATTN_SMEM_BYTES);

    cvt_inputs_kernel<<<(CVT_TOTAL + 255) / 256, 256>>>(
        (const float4*)x, (const float4*)Wq, (const float4*)Wk,
        (const float4*)Wv, (const float4*)Wo);
    copy_past_kernel<<<dim3(kHD / 32, kPAST / 32, kB * kG), dim3(32, 8)>>>(pk, pv);
    qkv_kernel<<<dim3(kNTOT / 128, kM / 128), 256, GEMM_SMEM>>>(rf, bq, bk, bv);
    attn_kernel<<<dim3(kLQ / 128, kH, kB), 256, ATTN_SMEM_BYTES>>>();
    out_kernel<<<dim3(kD / 128, kM / 128), 256, GEMM_SMEM>>>(bo, out);
}